// round 1
// baseline (speedup 1.0000x reference)
#include <cuda_runtime.h>
#include <cuda_bf16.h>
#include <cstdint>

// ---------------------------------------------------------------------------
// NonLocalBlock: B=4, C=64, C2=32, H=W=128.
//   theta = conv1x1(x, w_theta)                 [B,32,128,128]
//   phi   = maxpool2(conv1x1(x, w_phi))         [B,32,64,64]
//   g     = maxpool2(conv1x1(x, w_g))           [B,32,64,64]
//   y     = softmax(theta^T phi) g              (fused, flash-style)
//   out   = conv1x1(y, w_out) + b_out + x
// All fp32; attention inner loops use packed fma.rn.f32x2 (2x fp32 rate).
// ---------------------------------------------------------------------------

#define Bsz   4
#define Cin   64
#define C2d   32
#define HW    16384   // 128*128
#define HW4   4096    // 64*64
#define KT    128     // key tile
#define QB    256     // queries per CTA

typedef unsigned long long u64;

// Scratch (device globals: no allocations allowed)
__device__ float g_theta[Bsz * HW * C2d];   // [b][n][c2]   8 MB
__device__ float g_phi  [Bsz * HW4 * C2d];  // [b][m][c2]   2 MB
__device__ float g_g    [Bsz * HW4 * C2d];  // [b][m][c2]   2 MB
__device__ float g_y    [Bsz * HW * C2d];   // [b][n][c2]   8 MB

// ---------------- packed f32x2 helpers ----------------
__device__ __forceinline__ u64 pack2(float lo, float hi) {
    u64 r; asm("mov.b64 %0, {%1,%2};" : "=l"(r) : "f"(lo), "f"(hi)); return r;
}
__device__ __forceinline__ void unpack2(u64 v, float& lo, float& hi) {
    asm("mov.b64 {%0,%1}, %2;" : "=f"(lo), "=f"(hi) : "l"(v));
}
__device__ __forceinline__ u64 ffma2(u64 a, u64 b, u64 c) {
    u64 d; asm("fma.rn.f32x2 %0, %1, %2, %3;" : "=l"(d) : "l"(a), "l"(b), "l"(c)); return d;
}
__device__ __forceinline__ u64 fmul2(u64 a, u64 b) {
    u64 d; asm("mul.rn.f32x2 %0, %1, %2;" : "=l"(d) : "l"(a), "l"(b)); return d;
}
__device__ __forceinline__ u64 fadd2(u64 a, u64 b) {
    u64 d; asm("add.rn.f32x2 %0, %1, %2;" : "=l"(d) : "l"(a), "l"(b)); return d;
}

// ---------------- cp.async helpers ----------------
__device__ __forceinline__ void cp_async16(void* smem, const void* gmem) {
    unsigned sa = (unsigned)__cvta_generic_to_shared(smem);
    asm volatile("cp.async.cg.shared.global [%0], [%1], 16;" :: "r"(sa), "l"(gmem));
}
__device__ __forceinline__ void cp_commit() {
    asm volatile("cp.async.commit_group;");
}
template <int N>
__device__ __forceinline__ void cp_wait() {
    asm volatile("cp.async.wait_group %0;" :: "n"(N));
}

// ===========================================================================
// Kernel 1: theta = conv1x1(x, w_theta) + b_theta, stored as [b][n][32]
// ===========================================================================
__global__ void __launch_bounds__(256) conv_theta_kernel(
    const float* __restrict__ x, const float* __restrict__ w,
    const float* __restrict__ bias)
{
    __shared__ float ws[Cin * C2d];   // [c][o]
    __shared__ float bs[C2d];
    const int tid = threadIdx.x;
    for (int i = tid; i < Cin * C2d; i += 256) {
        int c = i >> 5, o = i & 31;
        ws[i] = w[o * Cin + c];
    }
    if (tid < C2d) bs[tid] = bias[tid];
    __syncthreads();

    const int p = blockIdx.x * 256 + tid;       // global pixel 0..65535
    const int b = p >> 14, n = p & (HW - 1);

    const float* xb = x + (size_t)b * Cin * HW + n;
    float acc[C2d];
#pragma unroll
    for (int o = 0; o < C2d; ++o) acc[o] = bs[o];

    const float4* ws4 = reinterpret_cast<const float4*>(ws);
    for (int c = 0; c < Cin; ++c) {
        float xv = xb[(size_t)c * HW];
#pragma unroll
        for (int k = 0; k < 8; ++k) {
            float4 wv = ws4[c * 8 + k];
            acc[4*k+0] = fmaf(xv, wv.x, acc[4*k+0]);
            acc[4*k+1] = fmaf(xv, wv.y, acc[4*k+1]);
            acc[4*k+2] = fmaf(xv, wv.z, acc[4*k+2]);
            acc[4*k+3] = fmaf(xv, wv.w, acc[4*k+3]);
        }
    }
    float4* dst = reinterpret_cast<float4*>(g_theta + (size_t)p * C2d);
#pragma unroll
    for (int i = 0; i < 8; ++i)
        dst[i] = make_float4(acc[4*i], acc[4*i+1], acc[4*i+2], acc[4*i+3]);
}

// ===========================================================================
// Kernel 2: phi = maxpool2(conv1x1(x,w_phi)), g = maxpool2(conv1x1(x,w_g))
// stored as [b][m][32], m over 64x64 pooled grid
// ===========================================================================
__global__ void __launch_bounds__(256) conv_pool_kernel(
    const float* __restrict__ x,
    const float* __restrict__ wphi, const float* __restrict__ bphi,
    const float* __restrict__ wg,   const float* __restrict__ bg)
{
    __shared__ float ws[2][Cin * C2d];
    __shared__ float bs[2][C2d];
    const int tid = threadIdx.x;
    for (int i = tid; i < Cin * C2d; i += 256) {
        int c = i >> 5, o = i & 31;
        ws[0][i] = wphi[o * Cin + c];
        ws[1][i] = wg[o * Cin + c];
    }
    if (tid < C2d) { bs[0][tid] = bphi[tid]; bs[1][tid] = bg[tid]; }
    __syncthreads();

    const int idx = blockIdx.x * 256 + tid;     // 0..16383
    const int b = idx >> 12, m = idx & (HW4 - 1);
    const int h2 = m >> 6, w2i = m & 63;
    const float* xb = x + (size_t)b * Cin * HW;

#pragma unroll 1
    for (int sel = 0; sel < 2; ++sel) {
        float mx[C2d];
#pragma unroll
        for (int o = 0; o < C2d; ++o) mx[o] = -3.0e38f;
        const float4* ws4 = reinterpret_cast<const float4*>(ws[sel]);
#pragma unroll 1
        for (int px = 0; px < 4; ++px) {
            const int n = (2 * h2 + (px >> 1)) * 128 + 2 * w2i + (px & 1);
            float acc[C2d];
#pragma unroll
            for (int o = 0; o < C2d; ++o) acc[o] = bs[sel][o];
            for (int c = 0; c < Cin; ++c) {
                float xv = xb[(size_t)c * HW + n];
#pragma unroll
                for (int k = 0; k < 8; ++k) {
                    float4 wv = ws4[c * 8 + k];
                    acc[4*k+0] = fmaf(xv, wv.x, acc[4*k+0]);
                    acc[4*k+1] = fmaf(xv, wv.y, acc[4*k+1]);
                    acc[4*k+2] = fmaf(xv, wv.z, acc[4*k+2]);
                    acc[4*k+3] = fmaf(xv, wv.w, acc[4*k+3]);
                }
            }
#pragma unroll
            for (int o = 0; o < C2d; ++o) mx[o] = fmaxf(mx[o], acc[o]);
        }
        float4* d4 = reinterpret_cast<float4*>((sel ? g_g : g_phi) + (size_t)idx * C2d);
#pragma unroll
        for (int i = 0; i < 8; ++i)
            d4[i] = make_float4(mx[4*i], mx[4*i+1], mx[4*i+2], mx[4*i+3]);
    }
}

// ===========================================================================
// Kernel 3: fused attention, flash-style online softmax.
// One thread per query; keys/values tiled through smem (double-buffered).
// All MACs via packed fma.rn.f32x2.
// ===========================================================================
__global__ void __launch_bounds__(256, 2) attn_kernel()
{
    extern __shared__ float sm[];   // 2 buffers x (KT*32 phi + KT*32 g) = 64 KB
    const int tid = threadIdx.x;
    const int b = blockIdx.y;
    const int q = blockIdx.x * QB + tid;

    // load query, pack into 16 f32x2 (c-pairs)
    const float4* qsrc = reinterpret_cast<const float4*>(
        g_theta + ((size_t)(b * HW + q)) * C2d);
    u64 qp[16];
#pragma unroll
    for (int i = 0; i < 8; ++i) {
        float4 v = qsrc[i];
        qp[2*i]   = pack2(v.x, v.y);
        qp[2*i+1] = pack2(v.z, v.w);
    }
    u64 yp[16];
#pragma unroll
    for (int j = 0; j < 16; ++j) yp[j] = 0ull;
    float mmax = -3.0e38f, lsum = 0.f;

    const float* base_phi = g_phi + (size_t)b * HW4 * C2d;
    const float* base_g   = g_g   + (size_t)b * HW4 * C2d;

    auto load_tile = [&](int t, int buf) {
        float* dphi = sm + buf * (KT * 64);
        float* dg   = dphi + KT * 32;
        const float* sphi = base_phi + (size_t)t * KT * 32;
        const float* sgg  = base_g   + (size_t)t * KT * 32;
        // KT*32 floats = 1024 float4 each; 256 threads -> 4 iters
#pragma unroll
        for (int i = 0; i < (KT * 32 / 4) / 256; ++i) {
            int id = tid + i * 256;
            cp_async16(dphi + id * 4, sphi + id * 4);
            cp_async16(dg   + id * 4, sgg  + id * 4);
        }
    };

    int buf = 0;
    load_tile(0, 0);
    cp_commit();
    const int NT = HW4 / KT;   // 32 tiles

    for (int t = 0; t < NT; ++t) {
        if (t + 1 < NT) { load_tile(t + 1, buf ^ 1); cp_commit(); cp_wait<1>(); }
        else            { cp_wait<0>(); }
        __syncthreads();

        const ulonglong2* ph = reinterpret_cast<const ulonglong2*>(sm + buf * (KT * 64));
        const ulonglong2* gg = reinterpret_cast<const ulonglong2*>(sm + buf * (KT * 64) + KT * 32);

#pragma unroll 1
        for (int m = 0; m < KT; ++m) {
            const ulonglong2* pr = ph + m * 8;      // 32 floats = 8 x u64x2
            ulonglong2 r0 = pr[0], r1 = pr[1], r2 = pr[2], r3 = pr[3];
            ulonglong2 r4 = pr[4], r5 = pr[5], r6 = pr[6], r7 = pr[7];
            // 4 independent FMA chains
            u64 a0 = fmul2(qp[0],  r0.x);
            u64 a1 = fmul2(qp[1],  r0.y);
            u64 a2 = fmul2(qp[2],  r1.x);
            u64 a3 = fmul2(qp[3],  r1.y);
            a0 = ffma2(qp[4],  r2.x, a0);
            a1 = ffma2(qp[5],  r2.y, a1);
            a2 = ffma2(qp[6],  r3.x, a2);
            a3 = ffma2(qp[7],  r3.y, a3);
            a0 = ffma2(qp[8],  r4.x, a0);
            a1 = ffma2(qp[9],  r4.y, a1);
            a2 = ffma2(qp[10], r5.x, a2);
            a3 = ffma2(qp[11], r5.y, a3);
            a0 = ffma2(qp[12], r6.x, a0);
            a1 = ffma2(qp[13], r6.y, a1);
            a2 = ffma2(qp[14], r7.x, a2);
            a3 = ffma2(qp[15], r7.y, a3);
            a0 = fadd2(a0, a1);
            a2 = fadd2(a2, a3);
            a0 = fadd2(a0, a2);
            float s0, s1; unpack2(a0, s0, s1);
            float s = s0 + s1;

            float p;
            if (s > mmax) {
                float corr = __expf(mmax - s);
                mmax = s;
                lsum = lsum * corr + 1.0f;
                u64 cc = pack2(corr, corr);
#pragma unroll
                for (int j = 0; j < 16; ++j) yp[j] = fmul2(yp[j], cc);
                p = 1.0f;
            } else {
                p = __expf(s - mmax);
                lsum += p;
            }
            u64 pp = pack2(p, p);
            const ulonglong2* gr = gg + m * 8;
#pragma unroll
            for (int k = 0; k < 8; ++k) {
                ulonglong2 gv = gr[k];
                yp[2*k]   = ffma2(pp, gv.x, yp[2*k]);
                yp[2*k+1] = ffma2(pp, gv.y, yp[2*k+1]);
            }
        }
        __syncthreads();
        buf ^= 1;
    }

    const float inv = 1.0f / lsum;
    const u64 ii = pack2(inv, inv);
    float4* ydst = reinterpret_cast<float4*>(g_y + ((size_t)(b * HW + q)) * C2d);
#pragma unroll
    for (int i = 0; i < 8; ++i) {
        u64 v0 = fmul2(yp[2*i],   ii);
        u64 v1 = fmul2(yp[2*i+1], ii);
        float4 o;
        unpack2(v0, o.x, o.y);
        unpack2(v1, o.z, o.w);
        ydst[i] = o;
    }
}

// ===========================================================================
// Kernel 4: out = conv1x1(y, w_out) + b_out + x   (residual)
// ===========================================================================
__global__ void __launch_bounds__(256) conv_out_kernel(
    const float* __restrict__ x, const float* __restrict__ w,
    const float* __restrict__ bias, float* __restrict__ out)
{
    __shared__ alignas(16) u64 w2[C2d * 32];  // [c2][k], pair (o=2k, 2k+1)
    __shared__ alignas(16) u64 bb[32];
    const int tid = threadIdx.x;
    for (int i = tid; i < C2d * 32; i += 256) {
        int c2 = i >> 5, k = i & 31;
        w2[i] = pack2(w[(2*k) * C2d + c2], w[(2*k+1) * C2d + c2]);
    }
    if (tid < 32) bb[tid] = pack2(bias[2*tid], bias[2*tid+1]);
    __syncthreads();

    const int p = blockIdx.x * 256 + tid;
    const int b = p >> 14, n = p & (HW - 1);

    u64 acc[32];
#pragma unroll
    for (int k = 0; k < 32; ++k) acc[k] = bb[k];

    const float4* ysrc = reinterpret_cast<const float4*>(g_y + (size_t)p * C2d);
#pragma unroll 1
    for (int i = 0; i < 8; ++i) {
        float4 yv = ysrc[i];
        float vs[4] = {yv.x, yv.y, yv.z, yv.w};
#pragma unroll
        for (int jj = 0; jj < 4; ++jj) {
            const int c2 = i * 4 + jj;
            u64 yy = pack2(vs[jj], vs[jj]);
            const ulonglong2* wr = reinterpret_cast<const ulonglong2*>(w2 + c2 * 32);
#pragma unroll
            for (int k = 0; k < 16; ++k) {
                ulonglong2 wv = wr[k];
                acc[2*k]   = ffma2(yy, wv.x, acc[2*k]);
                acc[2*k+1] = ffma2(yy, wv.y, acc[2*k+1]);
            }
        }
    }
    const float* xb = x + (size_t)b * Cin * HW + n;
    float* ob = out + (size_t)b * Cin * HW + n;
#pragma unroll
    for (int k = 0; k < 32; ++k) {
        float lo, hi; unpack2(acc[k], lo, hi);
        ob[(size_t)(2*k) * HW]   = lo + xb[(size_t)(2*k) * HW];
        ob[(size_t)(2*k+1) * HW] = hi + xb[(size_t)(2*k+1) * HW];
    }
}

// ===========================================================================
extern "C" void kernel_launch(void* const* d_in, const int* in_sizes, int n_in,
                              void* d_out, int out_size)
{
    const float* x       = (const float*)d_in[0];
    const float* w_theta = (const float*)d_in[1];
    const float* b_theta = (const float*)d_in[2];
    const float* w_phi   = (const float*)d_in[3];
    const float* b_phi   = (const float*)d_in[4];
    const float* w_g     = (const float*)d_in[5];
    const float* b_g     = (const float*)d_in[6];
    const float* w_out   = (const float*)d_in[7];
    const float* b_out   = (const float*)d_in[8];
    float* out = (float*)d_out;

    conv_theta_kernel<<<(Bsz * HW) / 256, 256>>>(x, w_theta, b_theta);
    conv_pool_kernel<<<(Bsz * HW4) / 256, 256>>>(x, w_phi, b_phi, w_g, b_g);

    const int smem_bytes = 2 * KT * 64 * (int)sizeof(float);   // 65536
    cudaFuncSetAttribute(attn_kernel,
                         cudaFuncAttributeMaxDynamicSharedMemorySize, smem_bytes);
    attn_kernel<<<dim3(HW / QB, Bsz), 256, smem_bytes>>>();

    conv_out_kernel<<<(Bsz * HW) / 256, 256>>>(x, w_out, b_out, out);
}

// round 2
// speedup vs baseline: 1.0029x; 1.0029x over previous
#include <cuda_runtime.h>
#include <cuda_bf16.h>
#include <cstdint>

// ---------------------------------------------------------------------------
// NonLocalBlock: B=4, C=64, C2=32, H=W=128.
//   theta = conv1x1(x, w_theta)                 [B,32,128,128]
//   phi   = maxpool2(conv1x1(x, w_phi))         [B,32,64,64]
//   g     = maxpool2(conv1x1(x, w_g))           [B,32,64,64]
//   y     = softmax(theta^T phi) g              (fused, flash-style)
//   out   = conv1x1(y, w_out) + b_out + x
// All fp32; attention inner loops use packed fma.rn.f32x2 (2x fp32 rate).
// ---------------------------------------------------------------------------

#define Bsz   4
#define Cin   64
#define C2d   32
#define HW    16384   // 128*128
#define HW4   4096    // 64*64
#define KT    128     // key tile
#define QB    256     // queries per CTA

typedef unsigned long long u64;

// Scratch (device globals: no allocations allowed)
__device__ float g_theta[Bsz * HW * C2d];   // [b][n][c2]   8 MB
__device__ float g_phi  [Bsz * HW4 * C2d];  // [b][m][c2]   2 MB
__device__ float g_g    [Bsz * HW4 * C2d];  // [b][m][c2]   2 MB
__device__ float g_y    [Bsz * HW * C2d];   // [b][n][c2]   8 MB

// ---------------- packed f32x2 helpers ----------------
__device__ __forceinline__ u64 pack2(float lo, float hi) {
    u64 r; asm("mov.b64 %0, {%1,%2};" : "=l"(r) : "f"(lo), "f"(hi)); return r;
}
__device__ __forceinline__ void unpack2(u64 v, float& lo, float& hi) {
    asm("mov.b64 {%0,%1}, %2;" : "=f"(lo), "=f"(hi) : "l"(v));
}
__device__ __forceinline__ u64 ffma2(u64 a, u64 b, u64 c) {
    u64 d; asm("fma.rn.f32x2 %0, %1, %2, %3;" : "=l"(d) : "l"(a), "l"(b), "l"(c)); return d;
}
__device__ __forceinline__ u64 fmul2(u64 a, u64 b) {
    u64 d; asm("mul.rn.f32x2 %0, %1, %2;" : "=l"(d) : "l"(a), "l"(b)); return d;
}
__device__ __forceinline__ u64 fadd2(u64 a, u64 b) {
    u64 d; asm("add.rn.f32x2 %0, %1, %2;" : "=l"(d) : "l"(a), "l"(b)); return d;
}

// ---------------- cp.async helpers ----------------
__device__ __forceinline__ void cp_async16(void* smem, const void* gmem) {
    unsigned sa = (unsigned)__cvta_generic_to_shared(smem);
    asm volatile("cp.async.cg.shared.global [%0], [%1], 16;" :: "r"(sa), "l"(gmem));
}
__device__ __forceinline__ void cp_commit() {
    asm volatile("cp.async.commit_group;");
}
template <int N>
__device__ __forceinline__ void cp_wait() {
    asm volatile("cp.async.wait_group %0;" :: "n"(N));
}

// ===========================================================================
// Kernel 1: theta = conv1x1(x, w_theta) + b_theta, stored as [b][n][32]
// ===========================================================================
__global__ void __launch_bounds__(256) conv_theta_kernel(
    const float* __restrict__ x, const float* __restrict__ w,
    const float* __restrict__ bias)
{
    __shared__ float ws[Cin * C2d];   // [c][o]
    __shared__ float bs[C2d];
    const int tid = threadIdx.x;
    for (int i = tid; i < Cin * C2d; i += 256) {
        int c = i >> 5, o = i & 31;
        ws[i] = w[o * Cin + c];
    }
    if (tid < C2d) bs[tid] = bias[tid];
    __syncthreads();

    const int p = blockIdx.x * 256 + tid;       // global pixel 0..65535
    const int b = p >> 14, n = p & (HW - 1);

    const float* xb = x + (size_t)b * Cin * HW + n;
    float acc[C2d];
#pragma unroll
    for (int o = 0; o < C2d; ++o) acc[o] = bs[o];

    const float4* ws4 = reinterpret_cast<const float4*>(ws);
    for (int c = 0; c < Cin; ++c) {
        float xv = xb[(size_t)c * HW];
#pragma unroll
        for (int k = 0; k < 8; ++k) {
            float4 wv = ws4[c * 8 + k];
            acc[4*k+0] = fmaf(xv, wv.x, acc[4*k+0]);
            acc[4*k+1] = fmaf(xv, wv.y, acc[4*k+1]);
            acc[4*k+2] = fmaf(xv, wv.z, acc[4*k+2]);
            acc[4*k+3] = fmaf(xv, wv.w, acc[4*k+3]);
        }
    }
    float4* dst = reinterpret_cast<float4*>(g_theta + (size_t)p * C2d);
#pragma unroll
    for (int i = 0; i < 8; ++i)
        dst[i] = make_float4(acc[4*i], acc[4*i+1], acc[4*i+2], acc[4*i+3]);
}

// ===========================================================================
// Kernel 2: phi = maxpool2(conv1x1(x,w_phi)), g = maxpool2(conv1x1(x,w_g))
// stored as [b][m][32], m over 64x64 pooled grid
// ===========================================================================
__global__ void __launch_bounds__(256) conv_pool_kernel(
    const float* __restrict__ x,
    const float* __restrict__ wphi, const float* __restrict__ bphi,
    const float* __restrict__ wg,   const float* __restrict__ bg)
{
    __shared__ float ws[2][Cin * C2d];
    __shared__ float bs[2][C2d];
    const int tid = threadIdx.x;
    for (int i = tid; i < Cin * C2d; i += 256) {
        int c = i >> 5, o = i & 31;
        ws[0][i] = wphi[o * Cin + c];
        ws[1][i] = wg[o * Cin + c];
    }
    if (tid < C2d) { bs[0][tid] = bphi[tid]; bs[1][tid] = bg[tid]; }
    __syncthreads();

    const int idx = blockIdx.x * 256 + tid;     // 0..16383
    const int b = idx >> 12, m = idx & (HW4 - 1);
    const int h2 = m >> 6, w2i = m & 63;
    const float* xb = x + (size_t)b * Cin * HW;

#pragma unroll 1
    for (int sel = 0; sel < 2; ++sel) {
        float mx[C2d];
#pragma unroll
        for (int o = 0; o < C2d; ++o) mx[o] = -3.0e38f;
        const float4* ws4 = reinterpret_cast<const float4*>(ws[sel]);
#pragma unroll 1
        for (int px = 0; px < 4; ++px) {
            const int n = (2 * h2 + (px >> 1)) * 128 + 2 * w2i + (px & 1);
            float acc[C2d];
#pragma unroll
            for (int o = 0; o < C2d; ++o) acc[o] = bs[sel][o];
            for (int c = 0; c < Cin; ++c) {
                float xv = xb[(size_t)c * HW + n];
#pragma unroll
                for (int k = 0; k < 8; ++k) {
                    float4 wv = ws4[c * 8 + k];
                    acc[4*k+0] = fmaf(xv, wv.x, acc[4*k+0]);
                    acc[4*k+1] = fmaf(xv, wv.y, acc[4*k+1]);
                    acc[4*k+2] = fmaf(xv, wv.z, acc[4*k+2]);
                    acc[4*k+3] = fmaf(xv, wv.w, acc[4*k+3]);
                }
            }
#pragma unroll
            for (int o = 0; o < C2d; ++o) mx[o] = fmaxf(mx[o], acc[o]);
        }
        float4* d4 = reinterpret_cast<float4*>((sel ? g_g : g_phi) + (size_t)idx * C2d);
#pragma unroll
        for (int i = 0; i < 8; ++i)
            d4[i] = make_float4(mx[4*i], mx[4*i+1], mx[4*i+2], mx[4*i+3]);
    }
}

// ===========================================================================
// Kernel 3: fused attention, flash-style online softmax.
// One thread per query; keys/values tiled through smem (double-buffered).
// All MACs via packed fma.rn.f32x2.
// ===========================================================================
__global__ void __launch_bounds__(256, 2) attn_kernel()
{
    extern __shared__ float sm[];   // 2 buffers x (KT*32 phi + KT*32 g) = 64 KB
    const int tid = threadIdx.x;
    const int b = blockIdx.y;
    const int q = blockIdx.x * QB + tid;

    // load query, pack into 16 f32x2 (c-pairs)
    const float4* qsrc = reinterpret_cast<const float4*>(
        g_theta + ((size_t)(b * HW + q)) * C2d);
    u64 qp[16];
#pragma unroll
    for (int i = 0; i < 8; ++i) {
        float4 v = qsrc[i];
        qp[2*i]   = pack2(v.x, v.y);
        qp[2*i+1] = pack2(v.z, v.w);
    }
    u64 yp[16];
#pragma unroll
    for (int j = 0; j < 16; ++j) yp[j] = 0ull;
    float mmax = -3.0e38f, lsum = 0.f;

    const float* base_phi = g_phi + (size_t)b * HW4 * C2d;
    const float* base_g   = g_g   + (size_t)b * HW4 * C2d;

    auto load_tile = [&](int t, int buf) {
        float* dphi = sm + buf * (KT * 64);
        float* dg   = dphi + KT * 32;
        const float* sphi = base_phi + (size_t)t * KT * 32;
        const float* sgg  = base_g   + (size_t)t * KT * 32;
        // KT*32 floats = 1024 float4 each; 256 threads -> 4 iters
#pragma unroll
        for (int i = 0; i < (KT * 32 / 4) / 256; ++i) {
            int id = tid + i * 256;
            cp_async16(dphi + id * 4, sphi + id * 4);
            cp_async16(dg   + id * 4, sgg  + id * 4);
        }
    };

    int buf = 0;
    load_tile(0, 0);
    cp_commit();
    const int NT = HW4 / KT;   // 32 tiles

    for (int t = 0; t < NT; ++t) {
        if (t + 1 < NT) { load_tile(t + 1, buf ^ 1); cp_commit(); cp_wait<1>(); }
        else            { cp_wait<0>(); }
        __syncthreads();

        const ulonglong2* ph = reinterpret_cast<const ulonglong2*>(sm + buf * (KT * 64));
        const ulonglong2* gg = reinterpret_cast<const ulonglong2*>(sm + buf * (KT * 64) + KT * 32);

#pragma unroll 1
        for (int m = 0; m < KT; ++m) {
            const ulonglong2* pr = ph + m * 8;      // 32 floats = 8 x u64x2
            ulonglong2 r0 = pr[0], r1 = pr[1], r2 = pr[2], r3 = pr[3];
            ulonglong2 r4 = pr[4], r5 = pr[5], r6 = pr[6], r7 = pr[7];
            // 4 independent FMA chains
            u64 a0 = fmul2(qp[0],  r0.x);
            u64 a1 = fmul2(qp[1],  r0.y);
            u64 a2 = fmul2(qp[2],  r1.x);
            u64 a3 = fmul2(qp[3],  r1.y);
            a0 = ffma2(qp[4],  r2.x, a0);
            a1 = ffma2(qp[5],  r2.y, a1);
            a2 = ffma2(qp[6],  r3.x, a2);
            a3 = ffma2(qp[7],  r3.y, a3);
            a0 = ffma2(qp[8],  r4.x, a0);
            a1 = ffma2(qp[9],  r4.y, a1);
            a2 = ffma2(qp[10], r5.x, a2);
            a3 = ffma2(qp[11], r5.y, a3);
            a0 = ffma2(qp[12], r6.x, a0);
            a1 = ffma2(qp[13], r6.y, a1);
            a2 = ffma2(qp[14], r7.x, a2);
            a3 = ffma2(qp[15], r7.y, a3);
            a0 = fadd2(a0, a1);
            a2 = fadd2(a2, a3);
            a0 = fadd2(a0, a2);
            float s0, s1; unpack2(a0, s0, s1);
            float s = s0 + s1;

            float p;
            if (s > mmax) {
                float corr = __expf(mmax - s);
                mmax = s;
                lsum = lsum * corr + 1.0f;
                u64 cc = pack2(corr, corr);
#pragma unroll
                for (int j = 0; j < 16; ++j) yp[j] = fmul2(yp[j], cc);
                p = 1.0f;
            } else {
                p = __expf(s - mmax);
                lsum += p;
            }
            u64 pp = pack2(p, p);
            const ulonglong2* gr = gg + m * 8;
#pragma unroll
            for (int k = 0; k < 8; ++k) {
                ulonglong2 gv = gr[k];
                yp[2*k]   = ffma2(pp, gv.x, yp[2*k]);
                yp[2*k+1] = ffma2(pp, gv.y, yp[2*k+1]);
            }
        }
        __syncthreads();
        buf ^= 1;
    }

    const float inv = 1.0f / lsum;
    const u64 ii = pack2(inv, inv);
    float4* ydst = reinterpret_cast<float4*>(g_y + ((size_t)(b * HW + q)) * C2d);
#pragma unroll
    for (int i = 0; i < 8; ++i) {
        u64 v0 = fmul2(yp[2*i],   ii);
        u64 v1 = fmul2(yp[2*i+1], ii);
        float4 o;
        unpack2(v0, o.x, o.y);
        unpack2(v1, o.z, o.w);
        ydst[i] = o;
    }
}

// ===========================================================================
// Kernel 4: out = conv1x1(y, w_out) + b_out + x   (residual)
// ===========================================================================
__global__ void __launch_bounds__(256) conv_out_kernel(
    const float* __restrict__ x, const float* __restrict__ w,
    const float* __restrict__ bias, float* __restrict__ out)
{
    __shared__ alignas(16) u64 w2[C2d * 32];  // [c2][k], pair (o=2k, 2k+1)
    __shared__ alignas(16) u64 bb[32];
    const int tid = threadIdx.x;
    for (int i = tid; i < C2d * 32; i += 256) {
        int c2 = i >> 5, k = i & 31;
        w2[i] = pack2(w[(2*k) * C2d + c2], w[(2*k+1) * C2d + c2]);
    }
    if (tid < 32) bb[tid] = pack2(bias[2*tid], bias[2*tid+1]);
    __syncthreads();

    const int p = blockIdx.x * 256 + tid;
    const int b = p >> 14, n = p & (HW - 1);

    u64 acc[32];
#pragma unroll
    for (int k = 0; k < 32; ++k) acc[k] = bb[k];

    const float4* ysrc = reinterpret_cast<const float4*>(g_y + (size_t)p * C2d);
#pragma unroll 1
    for (int i = 0; i < 8; ++i) {
        float4 yv = ysrc[i];
        float vs[4] = {yv.x, yv.y, yv.z, yv.w};
#pragma unroll
        for (int jj = 0; jj < 4; ++jj) {
            const int c2 = i * 4 + jj;
            u64 yy = pack2(vs[jj], vs[jj]);
            const ulonglong2* wr = reinterpret_cast<const ulonglong2*>(w2 + c2 * 32);
#pragma unroll
            for (int k = 0; k < 16; ++k) {
                ulonglong2 wv = wr[k];
                acc[2*k]   = ffma2(yy, wv.x, acc[2*k]);
                acc[2*k+1] = ffma2(yy, wv.y, acc[2*k+1]);
            }
        }
    }
    const float* xb = x + (size_t)b * Cin * HW + n;
    float* ob = out + (size_t)b * Cin * HW + n;
#pragma unroll
    for (int k = 0; k < 32; ++k) {
        float lo, hi; unpack2(acc[k], lo, hi);
        ob[(size_t)(2*k) * HW]   = lo + xb[(size_t)(2*k) * HW];
        ob[(size_t)(2*k+1) * HW] = hi + xb[(size_t)(2*k+1) * HW];
    }
}

// ===========================================================================
extern "C" void kernel_launch(void* const* d_in, const int* in_sizes, int n_in,
                              void* d_out, int out_size)
{
    const float* x       = (const float*)d_in[0];
    const float* w_theta = (const float*)d_in[1];
    const float* b_theta = (const float*)d_in[2];
    const float* w_phi   = (const float*)d_in[3];
    const float* b_phi   = (const float*)d_in[4];
    const float* w_g     = (const float*)d_in[5];
    const float* b_g     = (const float*)d_in[6];
    const float* w_out   = (const float*)d_in[7];
    const float* b_out   = (const float*)d_in[8];
    float* out = (float*)d_out;

    conv_theta_kernel<<<(Bsz * HW) / 256, 256>>>(x, w_theta, b_theta);
    conv_pool_kernel<<<(Bsz * HW4) / 256, 256>>>(x, w_phi, b_phi, w_g, b_g);

    const int smem_bytes = 2 * KT * 64 * (int)sizeof(float);   // 65536
    cudaFuncSetAttribute(attn_kernel,
                         cudaFuncAttributeMaxDynamicSharedMemorySize, smem_bytes);
    attn_kernel<<<dim3(HW / QB, Bsz), 256, smem_bytes>>>();

    conv_out_kernel<<<(Bsz * HW) / 256, 256>>>(x, w_out, b_out, out);
}

// round 4
// speedup vs baseline: 1.9209x; 1.9153x over previous
#include <cuda_runtime.h>
#include <cuda_bf16.h>
#include <cstdint>

#define Bsz   4
#define Cin   64
#define C2d   32
#define HW    16384
#define HW4   4096
#define NTI   32      // key tiles of 128

typedef unsigned int u32;

// Scratch (device globals)
__device__ __align__(1024) float g_theta[Bsz * HW  * C2d];  // swizzled 128B rows [n][32]
__device__ __align__(1024) float g_phi  [Bsz * HW4 * C2d];  // swizzled 128B rows [m][32]
__device__ __align__(1024) float g_gT   [Bsz * C2d * HW4];  // transposed [b][c][m], linear
__device__ __align__(1024) float g_y    [Bsz * HW  * C2d];  // linear [b][n][32]

// ---------------- helpers ----------------
__device__ __forceinline__ u32 smem_u32(const void* p) { return (u32)__cvta_generic_to_shared(p); }
__device__ __forceinline__ void cp16(u32 dst, const void* src) {
    asm volatile("cp.async.cg.shared.global [%0], [%1], 16;" :: "r"(dst), "l"(src));
}
__device__ __forceinline__ void cp_commit() { asm volatile("cp.async.commit_group;"); }
template <int N> __device__ __forceinline__ void cp_wait() {
    asm volatile("cp.async.wait_group %0;" :: "n"(N));
}
__device__ __forceinline__ void ldsm4(u32& r0, u32& r1, u32& r2, u32& r3, u32 a) {
    asm volatile("ldmatrix.sync.aligned.m8n8.x4.shared.b16 {%0,%1,%2,%3}, [%4];"
                 : "=r"(r0), "=r"(r1), "=r"(r2), "=r"(r3) : "r"(a));
}
__device__ __forceinline__ void ldsm2(u32& r0, u32& r1, u32 a) {
    asm volatile("ldmatrix.sync.aligned.m8n8.x2.shared.b16 {%0,%1}, [%2];"
                 : "=r"(r0), "=r"(r1) : "r"(a));
}
__device__ __forceinline__ u32 to_tf32(float f) {
    u32 r; asm("cvt.rna.tf32.f32 %0, %1;" : "=r"(r) : "f"(f)); return r;
}
__device__ __forceinline__ void mma_tf32(float* c, const u32* a, u32 b0, u32 b1) {
    asm volatile("mma.sync.aligned.m16n8k8.row.col.f32.tf32.tf32.f32 "
                 "{%0,%1,%2,%3}, {%4,%5,%6,%7}, {%8,%9}, {%0,%1,%2,%3};"
                 : "+f"(c[0]), "+f"(c[1]), "+f"(c[2]), "+f"(c[3])
                 : "r"(a[0]), "r"(a[1]), "r"(a[2]), "r"(a[3]), "r"(b0), "r"(b1));
}
__device__ __forceinline__ void sts64(u32 a, float x, float y) {
    asm volatile("st.shared.v2.f32 [%0], {%1,%2};" :: "r"(a), "f"(x), "f"(y) : "memory");
}

// ===========================================================================
// Kernel 1: theta (swizzled 128B rows)
// ===========================================================================
__global__ void __launch_bounds__(256) conv_theta_kernel(
    const float* __restrict__ x, const float* __restrict__ w, const float* __restrict__ bias)
{
    __shared__ float ws[Cin * C2d];
    __shared__ float bs[C2d];
    const int tid = threadIdx.x;
    for (int i = tid; i < Cin * C2d; i += 256) { int c = i >> 5, o = i & 31; ws[i] = w[o * Cin + c]; }
    if (tid < C2d) bs[tid] = bias[tid];
    __syncthreads();

    const int p = blockIdx.x * 256 + tid;
    const int b = p >> 14, n = p & (HW - 1);
    const float* xb = x + (size_t)b * Cin * HW + n;
    float acc[C2d];
#pragma unroll
    for (int o = 0; o < C2d; ++o) acc[o] = bs[o];
    const float4* ws4 = reinterpret_cast<const float4*>(ws);
    for (int c = 0; c < Cin; ++c) {
        float xv = xb[(size_t)c * HW];
#pragma unroll
        for (int k = 0; k < 8; ++k) {
            float4 wv = ws4[c * 8 + k];
            acc[4*k+0] = fmaf(xv, wv.x, acc[4*k+0]);
            acc[4*k+1] = fmaf(xv, wv.y, acc[4*k+1]);
            acc[4*k+2] = fmaf(xv, wv.z, acc[4*k+2]);
            acc[4*k+3] = fmaf(xv, wv.w, acc[4*k+3]);
        }
    }
    float4* dst = reinterpret_cast<float4*>(g_theta + (size_t)p * C2d);
    const int sw = p & 7;
#pragma unroll
    for (int j = 0; j < 8; ++j)
        dst[j ^ sw] = make_float4(acc[4*j], acc[4*j+1], acc[4*j+2], acc[4*j+3]);
}

// ===========================================================================
// Kernel 2: phi (swizzled rows) & gT (transposed [b][c][m])
// ===========================================================================
__global__ void __launch_bounds__(256) conv_pool_kernel(
    const float* __restrict__ x,
    const float* __restrict__ wphi, const float* __restrict__ bphi,
    const float* __restrict__ wg,   const float* __restrict__ bg)
{
    __shared__ float ws[2][Cin * C2d];
    __shared__ float bs[2][C2d];
    const int tid = threadIdx.x;
    for (int i = tid; i < Cin * C2d; i += 256) {
        int c = i >> 5, o = i & 31;
        ws[0][i] = wphi[o * Cin + c];
        ws[1][i] = wg[o * Cin + c];
    }
    if (tid < C2d) { bs[0][tid] = bphi[tid]; bs[1][tid] = bg[tid]; }
    __syncthreads();

    const int idx = blockIdx.x * 256 + tid;
    const int b = idx >> 12, m = idx & (HW4 - 1);
    const int h2 = m >> 6, w2i = m & 63;
    const float* xb = x + (size_t)b * Cin * HW;
    const int sw = idx & 7;

#pragma unroll 1
    for (int sel = 0; sel < 2; ++sel) {
        float mx[C2d];
#pragma unroll
        for (int o = 0; o < C2d; ++o) mx[o] = -3.0e38f;
        const float4* ws4 = reinterpret_cast<const float4*>(ws[sel]);
#pragma unroll 1
        for (int px = 0; px < 4; ++px) {
            const int n = (2 * h2 + (px >> 1)) * 128 + 2 * w2i + (px & 1);
            float acc[C2d];
#pragma unroll
            for (int o = 0; o < C2d; ++o) acc[o] = bs[sel][o];
            for (int c = 0; c < Cin; ++c) {
                float xv = xb[(size_t)c * HW + n];
#pragma unroll
                for (int k = 0; k < 8; ++k) {
                    float4 wv = ws4[c * 8 + k];
                    acc[4*k+0] = fmaf(xv, wv.x, acc[4*k+0]);
                    acc[4*k+1] = fmaf(xv, wv.y, acc[4*k+1]);
                    acc[4*k+2] = fmaf(xv, wv.z, acc[4*k+2]);
                    acc[4*k+3] = fmaf(xv, wv.w, acc[4*k+3]);
                }
            }
#pragma unroll
            for (int o = 0; o < C2d; ++o) mx[o] = fmaxf(mx[o], acc[o]);
        }
        if (sel == 0) {
            float4* d4 = reinterpret_cast<float4*>(g_phi + (size_t)idx * C2d);
#pragma unroll
            for (int j = 0; j < 8; ++j)
                d4[j ^ sw] = make_float4(mx[4*j], mx[4*j+1], mx[4*j+2], mx[4*j+3]);
        } else {
            float* dst = g_gT + (size_t)b * C2d * HW4 + m;
#pragma unroll
            for (int o = 0; o < C2d; ++o) dst[(size_t)o * HW4] = mx[o];
        }
    }
}

// ===========================================================================
// Kernel 3: flash attention on mma.sync tf32 (legacy tensor path).
// grid=(128,4), 256 thr (8 warps x 16 query rows).
// SMEM: Q 16K | KV 2x(phi16K + gT16K) | P 8x4K  = 112 KB
// ===========================================================================
#define OFF_Q   0
#define OFF_KV  16384
#define OFF_P   (16384 + 65536)
#define SMEM_AT (OFF_P + 32768)

__global__ void __launch_bounds__(256, 2) attn_mma_kernel()
{
    extern __shared__ __align__(1024) char smem[];
    const u32 sb = smem_u32(smem);
    const int tid = threadIdx.x, wid = tid >> 5, lane = tid & 31;
    const int b = blockIdx.y, q0 = blockIdx.x * 128;

    // stage Q (raw copy, pre-swizzled rows)
    {
        const char* gq = (const char*)(g_theta + (size_t)(b * HW + q0) * C2d);
#pragma unroll
        for (int i = 0; i < 4; ++i) {
            int idx = tid + 256 * i;
            cp16(sb + OFF_Q + (u32)idx * 16, gq + (size_t)idx * 16);
        }
    }
    cp_commit(); cp_wait<0>();
    __syncthreads();

    // extract Q A-frags, tf32 hi/lo split
    u32 qh[4][4], ql[4][4];
#pragma unroll
    for (int ks = 0; ks < 4; ++ks) {
        u32 row = (u32)(16 * wid + ((lane >> 3) & 1) * 8 + (lane & 7));
        u32 chunk = (u32)(2 * ks + (lane >> 4));
        u32 a = sb + OFF_Q + row * 128 + ((chunk ^ (lane & 7u))) * 16;
        u32 r[4];
        ldsm4(r[0], r[1], r[2], r[3], a);
#pragma unroll
        for (int i = 0; i < 4; ++i) {
            float f = __uint_as_float(r[i]);
            qh[ks][i] = to_tf32(f);
            ql[ks][i] = to_tf32(f - __uint_as_float(qh[ks][i]));
        }
    }

    auto load_kv = [&](int t, int bufi) {
        const char* sp = (const char*)(g_phi + (size_t)(b * HW4 + t * 128) * C2d);
        u32 dph = sb + OFF_KV + (u32)bufi * 32768;
#pragma unroll
        for (int i = 0; i < 4; ++i) {
            int idx = tid + 256 * i;
            cp16(dph + (u32)idx * 16, sp + (size_t)idx * 16);
        }
        const char* sg = (const char*)(g_gT + (size_t)b * C2d * HW4 + t * 128);
        u32 dg = dph + 16384;
#pragma unroll
        for (int i = 0; i < 4; ++i) {
            int idx = tid + 256 * i;
            int c = idx >> 5, j = idx & 31;
            cp16(dg + (u32)c * 512 + (u32)(j ^ (c & 7)) * 16,
                 sg + (size_t)c * HW4 * 4 + (size_t)j * 16);
        }
    };

    load_kv(0, 0);
    cp_commit();

    float ofrag[4][4];
#pragma unroll
    for (int nb = 0; nb < 4; ++nb)
#pragma unroll
        for (int i = 0; i < 4; ++i) ofrag[nb][i] = 0.f;
    float rsum0 = 0.f, rsum1 = 0.f;

    const u32 poff = sb + OFF_P + (u32)wid * 4096;
    const u32 Lm = (u32)(lane & 15);
    int buf = 0;

    for (int t = 0; t < NTI; ++t) {
        if (t + 1 < NTI) { load_kv(t + 1, buf ^ 1); cp_commit(); cp_wait<1>(); }
        else             { cp_wait<0>(); }
        __syncthreads();

        const u32 phioff = sb + OFF_KV + (u32)buf * 32768;
        const u32 goff = phioff + 16384;

#pragma unroll 1
        for (int half = 0; half < 2; ++half) {
            // --- QK: 8 n-blocks of 8 keys ---
#pragma unroll
            for (int j = 0; j < 8; ++j) {
                float s[4] = {0.f, 0.f, 0.f, 0.f};
                const u32 keyrow = (u32)(half * 64 + j * 8) + (Lm & 7u);
#pragma unroll
                for (int ks = 0; ks < 4; ++ks) {
                    u32 chunk = (u32)(2 * ks) + (Lm >> 3);
                    u32 a = phioff + keyrow * 128 + ((chunk ^ (Lm & 7u))) * 16;
                    u32 braw0, braw1;
                    ldsm2(braw0, braw1, a);
                    u32 kh0 = to_tf32(__uint_as_float(braw0));
                    u32 kh1 = to_tf32(__uint_as_float(braw1));
                    u32 kl0 = to_tf32(__uint_as_float(braw0) - __uint_as_float(kh0));
                    u32 kl1 = to_tf32(__uint_as_float(braw1) - __uint_as_float(kh1));
                    mma_tf32(s, qh[ks], kh0, kh1);
                    mma_tf32(s, ql[ks], kh0, kh1);
                    mma_tf32(s, qh[ks], kl0, kl1);
                }
                float p0 = __expf(s[0]), p1 = __expf(s[1]);
                float p2 = __expf(s[2]), p3 = __expf(s[3]);
                rsum0 += p0 + p1;
                rsum1 += p2 + p3;
                // store P: row r=lane/4 (+8), key col = 8j + 2q(+1)
                const u32 r = (u32)(lane >> 2), q = (u32)(lane & 3);
                u32 a0 = poff + r * 256 + (((u32)(2 * j) + (q >> 1)) ^ (r & 7u)) * 16 + (q & 1u) * 8;
                sts64(a0, p0, p1);
                sts64(a0 + 8 * 256, p2, p3);
            }
            __syncwarp();

            // --- PV: O += P * G ---
#pragma unroll
            for (int kk = 0; kk < 8; ++kk) {
                u32 prow = (u32)(((lane >> 3) & 1) * 8 + (lane & 7));
                u32 pchunk = (u32)(2 * kk + (lane >> 4));
                u32 pa = poff + prow * 256 + ((pchunk ^ (lane & 7u))) * 16;
                u32 pr[4];
                ldsm4(pr[0], pr[1], pr[2], pr[3], pa);
                u32 paf[4];
#pragma unroll
                for (int i = 0; i < 4; ++i) paf[i] = to_tf32(__uint_as_float(pr[i]));
#pragma unroll
                for (int nb = 0; nb < 4; ++nb) {
                    u32 crow = (u32)(nb * 8) + (Lm & 7u);
                    u32 gchunk = (u32)(16 * half + 2 * kk) + (Lm >> 3);
                    u32 ga = goff + crow * 512 + ((gchunk ^ (Lm & 7u))) * 16;
                    u32 g0, g1;
                    ldsm2(g0, g1, ga);
                    g0 = to_tf32(__uint_as_float(g0));
                    g1 = to_tf32(__uint_as_float(g1));
                    mma_tf32(ofrag[nb], paf, g0, g1);
                }
            }
            __syncwarp();
        }
        __syncthreads();
        buf ^= 1;
    }

    // reduce row sums across the quad
    rsum0 += __shfl_xor_sync(0xFFFFFFFF, rsum0, 1);
    rsum0 += __shfl_xor_sync(0xFFFFFFFF, rsum0, 2);
    rsum1 += __shfl_xor_sync(0xFFFFFFFF, rsum1, 1);
    rsum1 += __shfl_xor_sync(0xFFFFFFFF, rsum1, 2);
    const float inv0 = 1.0f / rsum0, inv1 = 1.0f / rsum1;

    const int r0 = q0 + 16 * wid + (lane >> 2);
    float* y0 = g_y + ((size_t)(b * HW + r0)) * C2d + 2 * (lane & 3);
    float* y1 = y0 + 8 * C2d;
#pragma unroll
    for (int nb = 0; nb < 4; ++nb) {
        float2 v0 = make_float2(ofrag[nb][0] * inv0, ofrag[nb][1] * inv0);
        float2 v1 = make_float2(ofrag[nb][2] * inv1, ofrag[nb][3] * inv1);
        *reinterpret_cast<float2*>(y0 + nb * 8) = v0;
        *reinterpret_cast<float2*>(y1 + nb * 8) = v1;
    }
}

// ===========================================================================
// Kernel 4: out = conv1x1(y, w_out) + b_out + x
// ===========================================================================
__global__ void __launch_bounds__(256) conv_out_kernel(
    const float* __restrict__ x, const float* __restrict__ w,
    const float* __restrict__ bias, float* __restrict__ out)
{
    __shared__ float ws[C2d * Cin];   // [c2][o]
    __shared__ float bs[Cin];
    const int tid = threadIdx.x;
    for (int i = tid; i < C2d * Cin; i += 256) { int c2 = i >> 6, o = i & 63; ws[i] = w[o * C2d + c2]; }
    if (tid < Cin) bs[tid] = bias[tid];
    __syncthreads();

    const int p = blockIdx.x * 256 + tid;
    const int b = p >> 14, n = p & (HW - 1);

    float acc[Cin];
#pragma unroll
    for (int o = 0; o < Cin; ++o) acc[o] = bs[o];

    const float4* ysrc = reinterpret_cast<const float4*>(g_y + (size_t)p * C2d);
#pragma unroll 1
    for (int i = 0; i < 8; ++i) {
        float4 yv = ysrc[i];
        float vs[4] = {yv.x, yv.y, yv.z, yv.w};
#pragma unroll
        for (int jj = 0; jj < 4; ++jj) {
            const int c2 = i * 4 + jj;
            const float4* wr = reinterpret_cast<const float4*>(ws + c2 * Cin);
            float yy = vs[jj];
#pragma unroll
            for (int k = 0; k < 16; ++k) {
                float4 wv = wr[k];
                acc[4*k+0] = fmaf(yy, wv.x, acc[4*k+0]);
                acc[4*k+1] = fmaf(yy, wv.y, acc[4*k+1]);
                acc[4*k+2] = fmaf(yy, wv.z, acc[4*k+2]);
                acc[4*k+3] = fmaf(yy, wv.w, acc[4*k+3]);
            }
        }
    }
    const float* xb = x + (size_t)b * Cin * HW + n;
    float* ob = out + (size_t)b * Cin * HW + n;
#pragma unroll
    for (int o = 0; o < Cin; ++o)
        ob[(size_t)o * HW] = acc[o] + xb[(size_t)o * HW];
}

// ===========================================================================
extern "C" void kernel_launch(void* const* d_in, const int* in_sizes, int n_in,
                              void* d_out, int out_size)
{
    const float* x       = (const float*)d_in[0];
    const float* w_theta = (const float*)d_in[1];
    const float* b_theta = (const float*)d_in[2];
    const float* w_phi   = (const float*)d_in[3];
    const float* b_phi   = (const float*)d_in[4];
    const float* w_g     = (const float*)d_in[5];
    const float* b_g     = (const float*)d_in[6];
    const float* w_out   = (const float*)d_in[7];
    const float* b_out   = (const float*)d_in[8];
    float* out = (float*)d_out;

    conv_theta_kernel<<<(Bsz * HW) / 256, 256>>>(x, w_theta, b_theta);
    conv_pool_kernel<<<(Bsz * HW4) / 256, 256>>>(x, w_phi, b_phi, w_g, b_g);

    cudaFuncSetAttribute(attn_mma_kernel,
                         cudaFuncAttributeMaxDynamicSharedMemorySize, SMEM_AT);
    attn_mma_kernel<<<dim3(128, Bsz), 256, SMEM_AT>>>();

    conv_out_kernel<<<(Bsz * HW) / 256, 256>>>(x, w_out, b_out, out);
}

// round 5
// speedup vs baseline: 3.5700x; 1.8585x over previous
#include <cuda_runtime.h>
#include <cuda_bf16.h>
#include <cstdint>

#define Bsz   4
#define Cin   64
#define C2d   32
#define HW    16384
#define HW4   4096
#define NTI   32      // key tiles of 128

typedef unsigned int u32;

// Scratch (device globals)
__device__ __align__(1024) float g_theta[Bsz * HW  * C2d];  // fp32, swizzled 128B rows [n][32]
__device__ __align__(1024) float g_phi  [Bsz * HW4 * C2d];  // tf32-rounded fp32, swizzled rows [m][32]
__device__ __align__(1024) uint4 g_gB4  [Bsz * HW4 * 4];    // bf16, custom-swizzled 64B/key
__device__ __align__(1024) float g_y    [Bsz * HW  * C2d];  // linear [b][n][32]

// ---------------- helpers ----------------
__device__ __forceinline__ u32 smem_u32(const void* p) { return (u32)__cvta_generic_to_shared(p); }
__device__ __forceinline__ void cp16(u32 dst, const void* src) {
    asm volatile("cp.async.cg.shared.global [%0], [%1], 16;" :: "r"(dst), "l"(src));
}
__device__ __forceinline__ void cp_commit() { asm volatile("cp.async.commit_group;"); }
template <int N> __device__ __forceinline__ void cp_wait() {
    asm volatile("cp.async.wait_group %0;" :: "n"(N));
}
__device__ __forceinline__ void ldsm4(u32& r0, u32& r1, u32& r2, u32& r3, u32 a) {
    asm volatile("ldmatrix.sync.aligned.m8n8.x4.shared.b16 {%0,%1,%2,%3}, [%4];"
                 : "=r"(r0), "=r"(r1), "=r"(r2), "=r"(r3) : "r"(a));
}
__device__ __forceinline__ void ldsm2(u32& r0, u32& r1, u32 a) {
    asm volatile("ldmatrix.sync.aligned.m8n8.x2.shared.b16 {%0,%1}, [%2];"
                 : "=r"(r0), "=r"(r1) : "r"(a));
}
__device__ __forceinline__ void ldsm2t(u32& r0, u32& r1, u32 a) {
    asm volatile("ldmatrix.sync.aligned.m8n8.x2.trans.shared.b16 {%0,%1}, [%2];"
                 : "=r"(r0), "=r"(r1) : "r"(a));
}
__device__ __forceinline__ u32 to_tf32(float f) {
    u32 r; asm("cvt.rna.tf32.f32 %0, %1;" : "=r"(r) : "f"(f)); return r;
}
__device__ __forceinline__ float t32f(float f) { return __uint_as_float(to_tf32(f)); }
__device__ __forceinline__ u32 pbf2(float lo, float hi) {
    u32 r; asm("cvt.rn.bf16x2.f32 %0, %1, %2;" : "=r"(r) : "f"(hi), "f"(lo)); return r;
}
__device__ __forceinline__ void mma_tf32(float* c, const u32* a, u32 b0, u32 b1) {
    asm volatile("mma.sync.aligned.m16n8k8.row.col.f32.tf32.tf32.f32 "
                 "{%0,%1,%2,%3}, {%4,%5,%6,%7}, {%8,%9}, {%0,%1,%2,%3};"
                 : "+f"(c[0]), "+f"(c[1]), "+f"(c[2]), "+f"(c[3])
                 : "r"(a[0]), "r"(a[1]), "r"(a[2]), "r"(a[3]), "r"(b0), "r"(b1));
}
__device__ __forceinline__ void mma_bf16(float* c, const u32* a, u32 b0, u32 b1) {
    asm volatile("mma.sync.aligned.m16n8k16.row.col.f32.bf16.bf16.f32 "
                 "{%0,%1,%2,%3}, {%4,%5,%6,%7}, {%8,%9}, {%0,%1,%2,%3};"
                 : "+f"(c[0]), "+f"(c[1]), "+f"(c[2]), "+f"(c[3])
                 : "r"(a[0]), "r"(a[1]), "r"(a[2]), "r"(a[3]), "r"(b0), "r"(b1));
}

// ===========================================================================
// Kernel 1: theta = conv1x1(x,w)+b, fp32 swizzled 128B rows
// ===========================================================================
__global__ void __launch_bounds__(128) conv_theta_kernel(
    const float* __restrict__ x, const float* __restrict__ w, const float* __restrict__ bias)
{
    __shared__ float ws[Cin * C2d];
    __shared__ float bs[C2d];
    const int tid = threadIdx.x;
    for (int i = tid; i < Cin * C2d; i += 128) { int c = i >> 5, o = i & 31; ws[i] = w[o * Cin + c]; }
    if (tid < C2d) bs[tid] = bias[tid];
    __syncthreads();

    const int p = blockIdx.x * 128 + tid;
    const int b = p >> 14, n = p & (HW - 1);
    const float* xb = x + (size_t)b * Cin * HW + n;
    float acc[C2d];
#pragma unroll
    for (int o = 0; o < C2d; ++o) acc[o] = bs[o];
    const float4* ws4 = reinterpret_cast<const float4*>(ws);
    for (int c = 0; c < Cin; ++c) {
        float xv = xb[(size_t)c * HW];
#pragma unroll
        for (int k = 0; k < 8; ++k) {
            float4 wv = ws4[c * 8 + k];
            acc[4*k+0] = fmaf(xv, wv.x, acc[4*k+0]);
            acc[4*k+1] = fmaf(xv, wv.y, acc[4*k+1]);
            acc[4*k+2] = fmaf(xv, wv.z, acc[4*k+2]);
            acc[4*k+3] = fmaf(xv, wv.w, acc[4*k+3]);
        }
    }
    float4* dst = reinterpret_cast<float4*>(g_theta + (size_t)p * C2d);
    const int sw = p & 7;
#pragma unroll
    for (int j = 0; j < 8; ++j)
        dst[j ^ sw] = make_float4(acc[4*j], acc[4*j+1], acc[4*j+2], acc[4*j+3]);
}

// ===========================================================================
// Kernel 2: phi (tf32-rounded, swizzled rows) & g (bf16 custom-swizzled)
// ===========================================================================
__global__ void __launch_bounds__(256) conv_pool_kernel(
    const float* __restrict__ x,
    const float* __restrict__ wphi, const float* __restrict__ bphi,
    const float* __restrict__ wg,   const float* __restrict__ bg)
{
    __shared__ float ws[2][Cin * C2d];
    __shared__ float bs[2][C2d];
    const int tid = threadIdx.x;
    for (int i = tid; i < Cin * C2d; i += 256) {
        int c = i >> 5, o = i & 31;
        ws[0][i] = wphi[o * Cin + c];
        ws[1][i] = wg[o * Cin + c];
    }
    if (tid < C2d) { bs[0][tid] = bphi[tid]; bs[1][tid] = bg[tid]; }
    __syncthreads();

    const int idx = blockIdx.x * 256 + tid;
    const int b = idx >> 12, m = idx & (HW4 - 1);
    const int h2 = m >> 6, w2i = m & 63;
    const float* xb = x + (size_t)b * Cin * HW;

#pragma unroll 1
    for (int sel = 0; sel < 2; ++sel) {
        float mx[C2d];
#pragma unroll
        for (int o = 0; o < C2d; ++o) mx[o] = -3.0e38f;
        const float4* ws4 = reinterpret_cast<const float4*>(ws[sel]);
#pragma unroll 1
        for (int px = 0; px < 4; ++px) {
            const int n = (2 * h2 + (px >> 1)) * 128 + 2 * w2i + (px & 1);
            float acc[C2d];
#pragma unroll
            for (int o = 0; o < C2d; ++o) acc[o] = bs[sel][o];
            for (int c = 0; c < Cin; ++c) {
                float xv = xb[(size_t)c * HW + n];
#pragma unroll
                for (int k = 0; k < 8; ++k) {
                    float4 wv = ws4[c * 8 + k];
                    acc[4*k+0] = fmaf(xv, wv.x, acc[4*k+0]);
                    acc[4*k+1] = fmaf(xv, wv.y, acc[4*k+1]);
                    acc[4*k+2] = fmaf(xv, wv.z, acc[4*k+2]);
                    acc[4*k+3] = fmaf(xv, wv.w, acc[4*k+3]);
                }
            }
#pragma unroll
            for (int o = 0; o < C2d; ++o) mx[o] = fmaxf(mx[o], acc[o]);
        }
        if (sel == 0) {
            const int sw = idx & 7;
            float4* d4 = reinterpret_cast<float4*>(g_phi + (size_t)idx * C2d);
#pragma unroll
            for (int j = 0; j < 8; ++j)
                d4[j ^ sw] = make_float4(t32f(mx[4*j]), t32f(mx[4*j+1]),
                                         t32f(mx[4*j+2]), t32f(mx[4*j+3]));
        } else {
            // bf16, tile = 128 keys; physical row = key>>1 (128B), half = key&1
            uint4* base = g_gB4 + ((size_t)b * HW4 + (size_t)(m & ~127)) * 4;
            const int ml = m & 127, row = ml >> 1, half = ml & 1;
#pragma unroll
            for (int c = 0; c < 4; ++c) {
                uint4 v;
                v.x = pbf2(mx[8*c+0], mx[8*c+1]);
                v.y = pbf2(mx[8*c+2], mx[8*c+3]);
                v.z = pbf2(mx[8*c+4], mx[8*c+5]);
                v.w = pbf2(mx[8*c+6], mx[8*c+7]);
                int chunk = (half * 4 + c) ^ (row & 7);
                base[row * 8 + chunk] = v;
            }
        }
    }
}

// ===========================================================================
// Kernel 3: flash attention. grid=(128,4), 256 thr (8 warps x m16, all keys).
// SMEM: Q 16K | 2 x (K 16K + G 8K) = 64 KB. No P buffer (register path).
// ===========================================================================
#define OFF_Q    0
#define OFF_KV   16384
#define KVSTRIDE 24576
#define SMEM_AT  (16384 + 2 * 24576)

__global__ void __launch_bounds__(256, 2) attn_mma_kernel()
{
    extern __shared__ __align__(1024) char smem[];
    const u32 sb = smem_u32(smem);
    const int tid = threadIdx.x, wid = tid >> 5, lane = tid & 31;
    const int b = blockIdx.y, q0 = blockIdx.x * 128;

    auto load_kv = [&](int t, int bufi) {
        u32 d = sb + OFF_KV + (u32)bufi * KVSTRIDE;
        const char* sp = (const char*)(g_phi + (size_t)(b * HW4 + t * 128) * C2d);
#pragma unroll
        for (int i = 0; i < 4; ++i) {
            int idx = tid + 256 * i;
            cp16(d + (u32)idx * 16, sp + (size_t)idx * 16);
        }
        const char* sg = (const char*)(g_gB4 + ((size_t)b * HW4 + (size_t)t * 128) * 4);
#pragma unroll
        for (int i = 0; i < 2; ++i) {
            int idx = tid + 256 * i;
            cp16(d + 16384 + (u32)idx * 16, sg + (size_t)idx * 16);
        }
    };

    // stage Q + KV tile 0
    {
        const char* gq = (const char*)(g_theta + (size_t)(b * HW + q0) * C2d);
#pragma unroll
        for (int i = 0; i < 4; ++i) {
            int idx = tid + 256 * i;
            cp16(sb + OFF_Q + (u32)idx * 16, gq + (size_t)idx * 16);
        }
    }
    load_kv(0, 0);
    cp_commit();
    cp_wait<0>();
    __syncthreads();

    // Q A-frags, fp32 hi/lo split (hi exactly tf32)
    u32 qh[4][4], ql[4][4];
#pragma unroll
    for (int ks = 0; ks < 4; ++ks) {
        u32 row = (u32)(16 * wid + ((lane >> 3) & 1) * 8 + (lane & 7));
        u32 chunk = (u32)(2 * ks + (lane >> 4));
        u32 a = sb + OFF_Q + row * 128 + ((chunk ^ (lane & 7u))) * 16;
        u32 r[4];
        ldsm4(r[0], r[1], r[2], r[3], a);
#pragma unroll
        for (int i = 0; i < 4; ++i) {
            float f = __uint_as_float(r[i]);
            qh[ks][i] = to_tf32(f);
            ql[ks][i] = to_tf32(f - __uint_as_float(qh[ks][i]));
        }
    }

    float ofrag[4][4];
#pragma unroll
    for (int nb = 0; nb < 4; ++nb)
#pragma unroll
        for (int i = 0; i < 4; ++i) ofrag[nb][i] = 0.f;
    float rsum0 = 0.f, rsum1 = 0.f;

    const u32 Lm = (u32)(lane & 15);
    int buf = 0;

    for (int t = 0; t < NTI; ++t) {
        if (t + 1 < NTI) { load_kv(t + 1, buf ^ 1); cp_commit(); cp_wait<1>(); }
        else             { cp_wait<0>(); }
        __syncthreads();

        const u32 Koff = sb + OFF_KV + (u32)buf * KVSTRIDE;
        const u32 Goff = Koff + 16384;

#pragma unroll
        for (int jp = 0; jp < 8; ++jp) {
            const u32 kb = (u32)(jp * 16);
            float s0[4] = {0.f, 0.f, 0.f, 0.f}, s1[4] = {0.f, 0.f, 0.f, 0.f};
            const u32 kr0 = kb + (Lm & 7u), kr1 = kr0 + 8;
#pragma unroll
            for (int ks = 0; ks < 4; ++ks) {
                u32 ch = (u32)(2 * ks) + (Lm >> 3);
                u32 a0 = Koff + kr0 * 128 + ((ch ^ (kr0 & 7u))) * 16;
                u32 a1 = Koff + kr1 * 128 + ((ch ^ (kr1 & 7u))) * 16;
                u32 x0, x1, y0, y1;
                ldsm2(x0, x1, a0);
                ldsm2(y0, y1, a1);
                mma_tf32(s0, qh[ks], x0, x1);
                mma_tf32(s1, qh[ks], y0, y1);
                mma_tf32(s0, ql[ks], x0, x1);
                mma_tf32(s1, ql[ks], y0, y1);
            }
            float e00 = __expf(s0[0]), e01 = __expf(s0[1]);
            float e02 = __expf(s0[2]), e03 = __expf(s0[3]);
            float e10 = __expf(s1[0]), e11 = __expf(s1[1]);
            float e12 = __expf(s1[2]), e13 = __expf(s1[3]);
            rsum0 += (e00 + e01) + (e10 + e11);
            rsum1 += (e02 + e03) + (e12 + e13);
            u32 pa[4];
            pa[0] = pbf2(e00, e01);   // rows r,   k cols 2q,2q+1  (block j)
            pa[1] = pbf2(e02, e03);   // rows r+8, k cols 2q,2q+1
            pa[2] = pbf2(e10, e11);   // rows r,   k cols 8+2q     (block j+1)
            pa[3] = pbf2(e12, e13);   // rows r+8, k cols 8+2q
            const u32 key = kb + Lm;
            const u32 grow = key >> 1, ghalf = key & 1u;
#pragma unroll
            for (int nb = 0; nb < 4; ++nb) {
                u32 chunk = ((ghalf << 2) + (u32)nb) ^ (grow & 7u);
                u32 ga = Goff + grow * 128 + chunk * 16;
                u32 g0, g1;
                ldsm2t(g0, g1, ga);
                mma_bf16(ofrag[nb], pa, g0, g1);
            }
        }
        __syncthreads();
        buf ^= 1;
    }

    rsum0 += __shfl_xor_sync(0xFFFFFFFF, rsum0, 1);
    rsum0 += __shfl_xor_sync(0xFFFFFFFF, rsum0, 2);
    rsum1 += __shfl_xor_sync(0xFFFFFFFF, rsum1, 1);
    rsum1 += __shfl_xor_sync(0xFFFFFFFF, rsum1, 2);
    const float inv0 = 1.0f / rsum0, inv1 = 1.0f / rsum1;

    const int r0 = q0 + 16 * wid + (lane >> 2);
    float* y0 = g_y + ((size_t)(b * HW + r0)) * C2d + 2 * (lane & 3);
    float* y1 = y0 + 8 * C2d;
#pragma unroll
    for (int nb = 0; nb < 4; ++nb) {
        *reinterpret_cast<float2*>(y0 + nb * 8) =
            make_float2(ofrag[nb][0] * inv0, ofrag[nb][1] * inv0);
        *reinterpret_cast<float2*>(y1 + nb * 8) =
            make_float2(ofrag[nb][2] * inv1, ofrag[nb][3] * inv1);
    }
}

// ===========================================================================
// Kernel 4: out = conv1x1(y, w_out) + b_out + x
// ===========================================================================
__global__ void __launch_bounds__(128) conv_out_kernel(
    const float* __restrict__ x, const float* __restrict__ w,
    const float* __restrict__ bias, float* __restrict__ out)
{
    __shared__ float ws[C2d * Cin];   // [c2][o]
    __shared__ float bs[Cin];
    const int tid = threadIdx.x;
    for (int i = tid; i < C2d * Cin; i += 128) { int c2 = i >> 6, o = i & 63; ws[i] = w[o * C2d + c2]; }
    if (tid < Cin) bs[tid] = bias[tid];
    __syncthreads();

    const int p = blockIdx.x * 128 + tid;
    const int b = p >> 14, n = p & (HW - 1);

    float acc[Cin];
#pragma unroll
    for (int o = 0; o < Cin; ++o) acc[o] = bs[o];

    const float4* ysrc = reinterpret_cast<const float4*>(g_y + (size_t)p * C2d);
#pragma unroll 1
    for (int i = 0; i < 8; ++i) {
        float4 yv = ysrc[i];
        float vs[4] = {yv.x, yv.y, yv.z, yv.w};
#pragma unroll
        for (int jj = 0; jj < 4; ++jj) {
            const int c2 = i * 4 + jj;
            const float4* wr = reinterpret_cast<const float4*>(ws + c2 * Cin);
            float yy = vs[jj];
#pragma unroll
            for (int k = 0; k < 16; ++k) {
                float4 wv = wr[k];
                acc[4*k+0] = fmaf(yy, wv.x, acc[4*k+0]);
                acc[4*k+1] = fmaf(yy, wv.y, acc[4*k+1]);
                acc[4*k+2] = fmaf(yy, wv.z, acc[4*k+2]);
                acc[4*k+3] = fmaf(yy, wv.w, acc[4*k+3]);
            }
        }
    }
    const float* xb = x + (size_t)b * Cin * HW + n;
    float* ob = out + (size_t)b * Cin * HW + n;
#pragma unroll
    for (int o = 0; o < Cin; ++o)
        ob[(size_t)o * HW] = acc[o] + xb[(size_t)o * HW];
}

// ===========================================================================
extern "C" void kernel_launch(void* const* d_in, const int* in_sizes, int n_in,
                              void* d_out, int out_size)
{
    const float* x       = (const float*)d_in[0];
    const float* w_theta = (const float*)d_in[1];
    const float* b_theta = (const float*)d_in[2];
    const float* w_phi   = (const float*)d_in[3];
    const float* b_phi   = (const float*)d_in[4];
    const float* w_g     = (const float*)d_in[5];
    const float* b_g     = (const float*)d_in[6];
    const float* w_out   = (const float*)d_in[7];
    const float* b_out   = (const float*)d_in[8];
    float* out = (float*)d_out;

    conv_theta_kernel<<<(Bsz * HW) / 128, 128>>>(x, w_theta, b_theta);
    conv_pool_kernel<<<(Bsz * HW4) / 256, 256>>>(x, w_phi, b_phi, w_g, b_g);

    cudaFuncSetAttribute(attn_mma_kernel,
                         cudaFuncAttributeMaxDynamicSharedMemorySize, SMEM_AT);
    attn_mma_kernel<<<dim3(128, Bsz), 256, SMEM_AT>>>();

    conv_out_kernel<<<(Bsz * HW) / 128, 128>>>(x, w_out, b_out, out);
}

// round 6
// speedup vs baseline: 4.5423x; 1.2724x over previous
#include <cuda_runtime.h>
#include <cuda_bf16.h>
#include <cstdint>

#define Bsz   4
#define Cin   64
#define C2d   32
#define HW    16384
#define HW4   4096
#define NTI   32      // key tiles of 128

typedef unsigned int u32;

// Scratch (device globals)
__device__ __align__(1024) float g_theta[Bsz * HW  * C2d];  // fp32, swizzled 128B rows [n][32]
__device__ __align__(1024) float g_phi  [Bsz * HW4 * C2d];  // tf32-rounded fp32, swizzled rows [m][32]
__device__ __align__(1024) uint4 g_gB4  [Bsz * HW4 * 4];    // bf16, custom-swizzled 64B/key
__device__ __align__(1024) float g_y    [Bsz * HW  * C2d];  // linear [b][n][32]

// ---------------- helpers ----------------
__device__ __forceinline__ u32 smem_u32(const void* p) { return (u32)__cvta_generic_to_shared(p); }
__device__ __forceinline__ void cp16(u32 dst, const void* src) {
    asm volatile("cp.async.cg.shared.global [%0], [%1], 16;" :: "r"(dst), "l"(src));
}
__device__ __forceinline__ void cp_commit() { asm volatile("cp.async.commit_group;"); }
template <int N> __device__ __forceinline__ void cp_wait() {
    asm volatile("cp.async.wait_group %0;" :: "n"(N));
}
__device__ __forceinline__ void ldsm4(u32& r0, u32& r1, u32& r2, u32& r3, u32 a) {
    asm volatile("ldmatrix.sync.aligned.m8n8.x4.shared.b16 {%0,%1,%2,%3}, [%4];"
                 : "=r"(r0), "=r"(r1), "=r"(r2), "=r"(r3) : "r"(a));
}
__device__ __forceinline__ void ldsm2(u32& r0, u32& r1, u32 a) {
    asm volatile("ldmatrix.sync.aligned.m8n8.x2.shared.b16 {%0,%1}, [%2];"
                 : "=r"(r0), "=r"(r1) : "r"(a));
}
__device__ __forceinline__ void ldsm2t(u32& r0, u32& r1, u32 a) {
    asm volatile("ldmatrix.sync.aligned.m8n8.x2.trans.shared.b16 {%0,%1}, [%2];"
                 : "=r"(r0), "=r"(r1) : "r"(a));
}
__device__ __forceinline__ u32 to_tf32(float f) {
    u32 r; asm("cvt.rna.tf32.f32 %0, %1;" : "=r"(r) : "f"(f)); return r;
}
__device__ __forceinline__ float t32f(float f) { return __uint_as_float(to_tf32(f)); }
__device__ __forceinline__ u32 pbf2(float lo, float hi) {
    u32 r; asm("cvt.rn.bf16x2.f32 %0, %1, %2;" : "=r"(r) : "f"(hi), "f"(lo)); return r;
}
__device__ __forceinline__ void mma_tf32(float* c, const u32* a, u32 b0, u32 b1) {
    asm volatile("mma.sync.aligned.m16n8k8.row.col.f32.tf32.tf32.f32 "
                 "{%0,%1,%2,%3}, {%4,%5,%6,%7}, {%8,%9}, {%0,%1,%2,%3};"
                 : "+f"(c[0]), "+f"(c[1]), "+f"(c[2]), "+f"(c[3])
                 : "r"(a[0]), "r"(a[1]), "r"(a[2]), "r"(a[3]), "r"(b0), "r"(b1));
}
__device__ __forceinline__ void mma_bf16(float* c, const u32* a, u32 b0, u32 b1) {
    asm volatile("mma.sync.aligned.m16n8k16.row.col.f32.bf16.bf16.f32 "
                 "{%0,%1,%2,%3}, {%4,%5,%6,%7}, {%8,%9}, {%0,%1,%2,%3};"
                 : "+f"(c[0]), "+f"(c[1]), "+f"(c[2]), "+f"(c[3])
                 : "r"(a[0]), "r"(a[1]), "r"(a[2]), "r"(a[3]), "r"(b0), "r"(b1));
}

// ===========================================================================
// Kernel 1: theta = conv1x1(x,w)+b, fp32 swizzled 128B rows (tf32-rounded)
// ===========================================================================
__global__ void __launch_bounds__(128) conv_theta_kernel(
    const float* __restrict__ x, const float* __restrict__ w, const float* __restrict__ bias)
{
    __shared__ float ws[Cin * C2d];
    __shared__ float bs[C2d];
    const int tid = threadIdx.x;
    for (int i = tid; i < Cin * C2d; i += 128) { int c = i >> 5, o = i & 31; ws[i] = w[o * Cin + c]; }
    if (tid < C2d) bs[tid] = bias[tid];
    __syncthreads();

    const int p = blockIdx.x * 128 + tid;
    const int b = p >> 14, n = p & (HW - 1);
    const float* xb = x + (size_t)b * Cin * HW + n;
    float acc[C2d];
#pragma unroll
    for (int o = 0; o < C2d; ++o) acc[o] = bs[o];
    const float4* ws4 = reinterpret_cast<const float4*>(ws);
    for (int c = 0; c < Cin; ++c) {
        float xv = xb[(size_t)c * HW];
#pragma unroll
        for (int k = 0; k < 8; ++k) {
            float4 wv = ws4[c * 8 + k];
            acc[4*k+0] = fmaf(xv, wv.x, acc[4*k+0]);
            acc[4*k+1] = fmaf(xv, wv.y, acc[4*k+1]);
            acc[4*k+2] = fmaf(xv, wv.z, acc[4*k+2]);
            acc[4*k+3] = fmaf(xv, wv.w, acc[4*k+3]);
        }
    }
    float4* dst = reinterpret_cast<float4*>(g_theta + (size_t)p * C2d);
    const int sw = p & 7;
#pragma unroll
    for (int j = 0; j < 8; ++j)
        dst[j ^ sw] = make_float4(t32f(acc[4*j]), t32f(acc[4*j+1]),
                                  t32f(acc[4*j+2]), t32f(acc[4*j+3]));
}

// ===========================================================================
// Kernel 2: phi (tf32-rounded, swizzled rows) & g (bf16 custom-swizzled)
// ===========================================================================
__global__ void __launch_bounds__(256) conv_pool_kernel(
    const float* __restrict__ x,
    const float* __restrict__ wphi, const float* __restrict__ bphi,
    const float* __restrict__ wg,   const float* __restrict__ bg)
{
    __shared__ float ws[2][Cin * C2d];
    __shared__ float bs[2][C2d];
    const int tid = threadIdx.x;
    for (int i = tid; i < Cin * C2d; i += 256) {
        int c = i >> 5, o = i & 31;
        ws[0][i] = wphi[o * Cin + c];
        ws[1][i] = wg[o * Cin + c];
    }
    if (tid < C2d) { bs[0][tid] = bphi[tid]; bs[1][tid] = bg[tid]; }
    __syncthreads();

    const int idx = blockIdx.x * 256 + tid;
    const int b = idx >> 12, m = idx & (HW4 - 1);
    const int h2 = m >> 6, w2i = m & 63;
    const float* xb = x + (size_t)b * Cin * HW;

#pragma unroll 1
    for (int sel = 0; sel < 2; ++sel) {
        float mx[C2d];
#pragma unroll
        for (int o = 0; o < C2d; ++o) mx[o] = -3.0e38f;
        const float4* ws4 = reinterpret_cast<const float4*>(ws[sel]);
#pragma unroll 1
        for (int px = 0; px < 4; ++px) {
            const int n = (2 * h2 + (px >> 1)) * 128 + 2 * w2i + (px & 1);
            float acc[C2d];
#pragma unroll
            for (int o = 0; o < C2d; ++o) acc[o] = bs[sel][o];
            for (int c = 0; c < Cin; ++c) {
                float xv = xb[(size_t)c * HW + n];
#pragma unroll
                for (int k = 0; k < 8; ++k) {
                    float4 wv = ws4[c * 8 + k];
                    acc[4*k+0] = fmaf(xv, wv.x, acc[4*k+0]);
                    acc[4*k+1] = fmaf(xv, wv.y, acc[4*k+1]);
                    acc[4*k+2] = fmaf(xv, wv.z, acc[4*k+2]);
                    acc[4*k+3] = fmaf(xv, wv.w, acc[4*k+3]);
                }
            }
#pragma unroll
            for (int o = 0; o < C2d; ++o) mx[o] = fmaxf(mx[o], acc[o]);
        }
        if (sel == 0) {
            const int sw = idx & 7;
            float4* d4 = reinterpret_cast<float4*>(g_phi + (size_t)idx * C2d);
#pragma unroll
            for (int j = 0; j < 8; ++j)
                d4[j ^ sw] = make_float4(t32f(mx[4*j]), t32f(mx[4*j+1]),
                                         t32f(mx[4*j+2]), t32f(mx[4*j+3]));
        } else {
            // bf16, tile = 128 keys; physical row = key>>1 (128B), half = key&1
            uint4* base = g_gB4 + ((size_t)b * HW4 + (size_t)(m & ~127)) * 4;
            const int ml = m & 127, row = ml >> 1, half = ml & 1;
#pragma unroll
            for (int c = 0; c < 4; ++c) {
                uint4 v;
                v.x = pbf2(mx[8*c+0], mx[8*c+1]);
                v.y = pbf2(mx[8*c+2], mx[8*c+3]);
                v.z = pbf2(mx[8*c+4], mx[8*c+5]);
                v.w = pbf2(mx[8*c+6], mx[8*c+7]);
                int chunk = (half * 4 + c) ^ (row & 7);
                base[row * 8 + chunk] = v;
            }
        }
    }
}

// ===========================================================================
// Kernel 3: flash attention. grid=(128,4), 256 thr (8 warps x m16, all keys).
// Single-pass tf32 QK (operands pre-rounded), bf16 PV via register P.
// SMEM: Q 16K | 2 x (K 16K + G 8K) = 64 KB.
// ===========================================================================
#define OFF_Q    0
#define OFF_KV   16384
#define KVSTRIDE 24576
#define SMEM_AT  (16384 + 2 * 24576)

__global__ void __launch_bounds__(256, 2) attn_mma_kernel()
{
    extern __shared__ __align__(1024) char smem[];
    const u32 sb = smem_u32(smem);
    const int tid = threadIdx.x, wid = tid >> 5, lane = tid & 31;
    const int b = blockIdx.y, q0 = blockIdx.x * 128;

    auto load_kv = [&](int t, int bufi) {
        u32 d = sb + OFF_KV + (u32)bufi * KVSTRIDE;
        const char* sp = (const char*)(g_phi + (size_t)(b * HW4 + t * 128) * C2d);
#pragma unroll
        for (int i = 0; i < 4; ++i) {
            int idx = tid + 256 * i;
            cp16(d + (u32)idx * 16, sp + (size_t)idx * 16);
        }
        const char* sg = (const char*)(g_gB4 + ((size_t)b * HW4 + (size_t)t * 128) * 4);
#pragma unroll
        for (int i = 0; i < 2; ++i) {
            int idx = tid + 256 * i;
            cp16(d + 16384 + (u32)idx * 16, sg + (size_t)idx * 16);
        }
    };

    // stage Q + KV tile 0
    {
        const char* gq = (const char*)(g_theta + (size_t)(b * HW + q0) * C2d);
#pragma unroll
        for (int i = 0; i < 4; ++i) {
            int idx = tid + 256 * i;
            cp16(sb + OFF_Q + (u32)idx * 16, gq + (size_t)idx * 16);
        }
    }
    load_kv(0, 0);
    cp_commit();
    cp_wait<0>();
    __syncthreads();

    // Q A-frags (already tf32-rounded by producer)
    u32 qh[4][4];
#pragma unroll
    for (int ks = 0; ks < 4; ++ks) {
        u32 row = (u32)(16 * wid + ((lane >> 3) & 1) * 8 + (lane & 7));
        u32 chunk = (u32)(2 * ks + (lane >> 4));
        u32 a = sb + OFF_Q + row * 128 + ((chunk ^ (lane & 7u))) * 16;
        ldsm4(qh[ks][0], qh[ks][1], qh[ks][2], qh[ks][3], a);
    }

    float ofrag[4][4];
#pragma unroll
    for (int nb = 0; nb < 4; ++nb)
#pragma unroll
        for (int i = 0; i < 4; ++i) ofrag[nb][i] = 0.f;
    float rsum0 = 0.f, rsum1 = 0.f;

    const u32 Lm = (u32)(lane & 15);
    int buf = 0;

    for (int t = 0; t < NTI; ++t) {
        if (t + 1 < NTI) { load_kv(t + 1, buf ^ 1); cp_commit(); cp_wait<1>(); }
        else             { cp_wait<0>(); }
        __syncthreads();

        const u32 Koff = sb + OFF_KV + (u32)buf * KVSTRIDE;
        const u32 Goff = Koff + 16384;

#pragma unroll
        for (int jp = 0; jp < 8; ++jp) {
            const u32 kb = (u32)(jp * 16);
            float s0[4] = {0.f, 0.f, 0.f, 0.f}, s1[4] = {0.f, 0.f, 0.f, 0.f};
            const u32 kr0 = kb + (Lm & 7u), kr1 = kr0 + 8;
#pragma unroll
            for (int ks = 0; ks < 4; ++ks) {
                u32 ch = (u32)(2 * ks) + (Lm >> 3);
                u32 a0 = Koff + kr0 * 128 + ((ch ^ (kr0 & 7u))) * 16;
                u32 a1 = Koff + kr1 * 128 + ((ch ^ (kr1 & 7u))) * 16;
                u32 x0, x1, y0, y1;
                ldsm2(x0, x1, a0);
                ldsm2(y0, y1, a1);
                mma_tf32(s0, qh[ks], x0, x1);
                mma_tf32(s1, qh[ks], y0, y1);
            }
            float e00 = __expf(s0[0]), e01 = __expf(s0[1]);
            float e02 = __expf(s0[2]), e03 = __expf(s0[3]);
            float e10 = __expf(s1[0]), e11 = __expf(s1[1]);
            float e12 = __expf(s1[2]), e13 = __expf(s1[3]);
            rsum0 += (e00 + e01) + (e10 + e11);
            rsum1 += (e02 + e03) + (e12 + e13);
            u32 pa[4];
            pa[0] = pbf2(e00, e01);   // rows r,   k cols 2q,2q+1  (block j)
            pa[1] = pbf2(e02, e03);   // rows r+8, k cols 2q,2q+1
            pa[2] = pbf2(e10, e11);   // rows r,   k cols 8+2q     (block j+1)
            pa[3] = pbf2(e12, e13);   // rows r+8, k cols 8+2q
            const u32 key = kb + Lm;
            const u32 grow = key >> 1, ghalf = key & 1u;
#pragma unroll
            for (int nb = 0; nb < 4; ++nb) {
                u32 chunk = ((ghalf << 2) + (u32)nb) ^ (grow & 7u);
                u32 ga = Goff + grow * 128 + chunk * 16;
                u32 g0, g1;
                ldsm2t(g0, g1, ga);
                mma_bf16(ofrag[nb], pa, g0, g1);
            }
        }
        __syncthreads();
        buf ^= 1;
    }

    rsum0 += __shfl_xor_sync(0xFFFFFFFF, rsum0, 1);
    rsum0 += __shfl_xor_sync(0xFFFFFFFF, rsum0, 2);
    rsum1 += __shfl_xor_sync(0xFFFFFFFF, rsum1, 1);
    rsum1 += __shfl_xor_sync(0xFFFFFFFF, rsum1, 2);
    const float inv0 = 1.0f / rsum0, inv1 = 1.0f / rsum1;

    const int r0 = q0 + 16 * wid + (lane >> 2);
    float* y0 = g_y + ((size_t)(b * HW + r0)) * C2d + 2 * (lane & 3);
    float* y1 = y0 + 8 * C2d;
#pragma unroll
    for (int nb = 0; nb < 4; ++nb) {
        *reinterpret_cast<float2*>(y0 + nb * 8) =
            make_float2(ofrag[nb][0] * inv0, ofrag[nb][1] * inv0);
        *reinterpret_cast<float2*>(y1 + nb * 8) =
            make_float2(ofrag[nb][2] * inv1, ofrag[nb][3] * inv1);
    }
}

// ===========================================================================
// Kernel 4: out = conv1x1(y, w_out) + b_out + x
// ===========================================================================
__global__ void __launch_bounds__(128) conv_out_kernel(
    const float* __restrict__ x, const float* __restrict__ w,
    const float* __restrict__ bias, float* __restrict__ out)
{
    __shared__ float ws[C2d * Cin];   // [c2][o]
    __shared__ float bs[Cin];
    const int tid = threadIdx.x;
    for (int i = tid; i < C2d * Cin; i += 128) { int c2 = i >> 6, o = i & 63; ws[i] = w[o * C2d + c2]; }
    if (tid < Cin) bs[tid] = bias[tid];
    __syncthreads();

    const int p = blockIdx.x * 128 + tid;
    const int b = p >> 14, n = p & (HW - 1);

    float acc[Cin];
#pragma unroll
    for (int o = 0; o < Cin; ++o) acc[o] = bs[o];

    const float4* ysrc = reinterpret_cast<const float4*>(g_y + (size_t)p * C2d);
#pragma unroll 1
    for (int i = 0; i < 8; ++i) {
        float4 yv = ysrc[i];
        float vs[4] = {yv.x, yv.y, yv.z, yv.w};
#pragma unroll
        for (int jj = 0; jj < 4; ++jj) {
            const int c2 = i * 4 + jj;
            const float4* wr = reinterpret_cast<const float4*>(ws + c2 * Cin);
            float yy = vs[jj];
#pragma unroll
            for (int k = 0; k < 16; ++k) {
                float4 wv = wr[k];
                acc[4*k+0] = fmaf(yy, wv.x, acc[4*k+0]);
                acc[4*k+1] = fmaf(yy, wv.y, acc[4*k+1]);
                acc[4*k+2] = fmaf(yy, wv.z, acc[4*k+2]);
                acc[4*k+3] = fmaf(yy, wv.w, acc[4*k+3]);
            }
        }
    }
    const float* xb = x + (size_t)b * Cin * HW + n;
    float* ob = out + (size_t)b * Cin * HW + n;
#pragma unroll
    for (int o = 0; o < Cin; ++o)
        ob[(size_t)o * HW] = acc[o] + xb[(size_t)o * HW];
}

// ===========================================================================
extern "C" void kernel_launch(void* const* d_in, const int* in_sizes, int n_in,
                              void* d_out, int out_size)
{
    const float* x       = (const float*)d_in[0];
    const float* w_theta = (const float*)d_in[1];
    const float* b_theta = (const float*)d_in[2];
    const float* w_phi   = (const float*)d_in[3];
    const float* b_phi   = (const float*)d_in[4];
    const float* w_g     = (const float*)d_in[5];
    const float* b_g     = (const float*)d_in[6];
    const float* w_out   = (const float*)d_in[7];
    const float* b_out   = (const float*)d_in[8];
    float* out = (float*)d_out;

    conv_theta_kernel<<<(Bsz * HW) / 128, 128>>>(x, w_theta, b_theta);
    conv_pool_kernel<<<(Bsz * HW4) / 256, 256>>>(x, w_phi, b_phi, w_g, b_g);

    cudaFuncSetAttribute(attn_mma_kernel,
                         cudaFuncAttributeMaxDynamicSharedMemorySize, SMEM_AT);
    attn_mma_kernel<<<dim3(128, Bsz), 256, SMEM_AT>>>();

    conv_out_kernel<<<(Bsz * HW) / 128, 128>>>(x, w_out, b_out, out);
}

// round 7
// speedup vs baseline: 4.5483x; 1.0013x over previous
#include <cuda_runtime.h>
#include <cuda_bf16.h>
#include <cstdint>

#define Bsz   4
#define Cin   64
#define C2d   32
#define HW    16384
#define HW4   4096
#define NTI   32      // key tiles of 128

typedef unsigned int u32;

// Scratch (device globals)
__device__ __align__(1024) float g_phi [Bsz * HW4 * C2d];  // tf32-rounded fp32, swizzled rows [m][32]
__device__ __align__(1024) uint4 g_gB4 [Bsz * HW4 * 4];    // bf16, custom-swizzled 64B/key

// ---------------- helpers ----------------
__device__ __forceinline__ u32 smem_u32(const void* p) { return (u32)__cvta_generic_to_shared(p); }
__device__ __forceinline__ void cp16(u32 dst, const void* src) {
    asm volatile("cp.async.cg.shared.global [%0], [%1], 16;" :: "r"(dst), "l"(src));
}
__device__ __forceinline__ void cp_commit() { asm volatile("cp.async.commit_group;"); }
template <int N> __device__ __forceinline__ void cp_wait() {
    asm volatile("cp.async.wait_group %0;" :: "n"(N));
}
__device__ __forceinline__ void ldsm4(u32& r0, u32& r1, u32& r2, u32& r3, u32 a) {
    asm volatile("ldmatrix.sync.aligned.m8n8.x4.shared.b16 {%0,%1,%2,%3}, [%4];"
                 : "=r"(r0), "=r"(r1), "=r"(r2), "=r"(r3) : "r"(a));
}
__device__ __forceinline__ void ldsm2(u32& r0, u32& r1, u32 a) {
    asm volatile("ldmatrix.sync.aligned.m8n8.x2.shared.b16 {%0,%1}, [%2];"
                 : "=r"(r0), "=r"(r1) : "r"(a));
}
__device__ __forceinline__ void ldsm2t(u32& r0, u32& r1, u32 a) {
    asm volatile("ldmatrix.sync.aligned.m8n8.x2.trans.shared.b16 {%0,%1}, [%2];"
                 : "=r"(r0), "=r"(r1) : "r"(a));
}
__device__ __forceinline__ u32 to_tf32(float f) {
    u32 r; asm("cvt.rna.tf32.f32 %0, %1;" : "=r"(r) : "f"(f)); return r;
}
__device__ __forceinline__ float t32f(float f) { return __uint_as_float(to_tf32(f)); }
__device__ __forceinline__ u32 pbf2(float lo, float hi) {
    u32 r; asm("cvt.rn.bf16x2.f32 %0, %1, %2;" : "=r"(r) : "f"(hi), "f"(lo)); return r;
}
__device__ __forceinline__ float ex2f(float x) {
    float r; asm("ex2.approx.f32 %0, %1;" : "=f"(r) : "f"(x)); return r;
}
__device__ __forceinline__ void sts128(u32 a, u32 c0, u32 c1, u32 c2, u32 c3) {
    asm volatile("st.shared.v4.b32 [%0], {%1,%2,%3,%4};"
                 :: "r"(a), "r"(c0), "r"(c1), "r"(c2), "r"(c3) : "memory");
}
__device__ __forceinline__ void sts64f(u32 a, float x, float y) {
    asm volatile("st.shared.v2.f32 [%0], {%1,%2};" :: "r"(a), "f"(x), "f"(y) : "memory");
}
__device__ __forceinline__ void lds128f(float& a, float& b, float& c, float& d, u32 addr) {
    asm volatile("ld.shared.v4.f32 {%0,%1,%2,%3}, [%4];"
                 : "=f"(a), "=f"(b), "=f"(c), "=f"(d) : "r"(addr));
}
__device__ __forceinline__ void mma_tf32(float* c, const u32* a, u32 b0, u32 b1) {
    asm volatile("mma.sync.aligned.m16n8k8.row.col.f32.tf32.tf32.f32 "
                 "{%0,%1,%2,%3}, {%4,%5,%6,%7}, {%8,%9}, {%0,%1,%2,%3};"
                 : "+f"(c[0]), "+f"(c[1]), "+f"(c[2]), "+f"(c[3])
                 : "r"(a[0]), "r"(a[1]), "r"(a[2]), "r"(a[3]), "r"(b0), "r"(b1));
}
__device__ __forceinline__ void mma_bf16(float* c, const u32* a, u32 b0, u32 b1) {
    asm volatile("mma.sync.aligned.m16n8k16.row.col.f32.bf16.bf16.f32 "
                 "{%0,%1,%2,%3}, {%4,%5,%6,%7}, {%8,%9}, {%0,%1,%2,%3};"
                 : "+f"(c[0]), "+f"(c[1]), "+f"(c[2]), "+f"(c[3])
                 : "r"(a[0]), "r"(a[1]), "r"(a[2]), "r"(a[3]), "r"(b0), "r"(b1));
}

// ===========================================================================
// Kernel 1: phi (tf32-rounded, swizzled rows) & g (bf16 custom-swizzled)
// ===========================================================================
__global__ void __launch_bounds__(256) conv_pool_kernel(
    const float* __restrict__ x,
    const float* __restrict__ wphi, const float* __restrict__ bphi,
    const float* __restrict__ wg,   const float* __restrict__ bg)
{
    __shared__ float ws[2][Cin * C2d];
    __shared__ float bs[2][C2d];
    const int tid = threadIdx.x;
    for (int i = tid; i < Cin * C2d; i += 256) {
        int c = i >> 5, o = i & 31;
        ws[0][i] = wphi[o * Cin + c];
        ws[1][i] = wg[o * Cin + c];
    }
    if (tid < C2d) { bs[0][tid] = bphi[tid]; bs[1][tid] = bg[tid]; }
    __syncthreads();

    const int idx = blockIdx.x * 256 + tid;
    const int b = idx >> 12, m = idx & (HW4 - 1);
    const int h2 = m >> 6, w2i = m & 63;
    const float* xb = x + (size_t)b * Cin * HW;

#pragma unroll 1
    for (int sel = 0; sel < 2; ++sel) {
        float mx[C2d];
#pragma unroll
        for (int o = 0; o < C2d; ++o) mx[o] = -3.0e38f;
        const float4* ws4 = reinterpret_cast<const float4*>(ws[sel]);
#pragma unroll 1
        for (int px = 0; px < 4; ++px) {
            const int n = (2 * h2 + (px >> 1)) * 128 + 2 * w2i + (px & 1);
            float acc[C2d];
#pragma unroll
            for (int o = 0; o < C2d; ++o) acc[o] = bs[sel][o];
            for (int c = 0; c < Cin; ++c) {
                float xv = xb[(size_t)c * HW + n];
#pragma unroll
                for (int k = 0; k < 8; ++k) {
                    float4 wv = ws4[c * 8 + k];
                    acc[4*k+0] = fmaf(xv, wv.x, acc[4*k+0]);
                    acc[4*k+1] = fmaf(xv, wv.y, acc[4*k+1]);
                    acc[4*k+2] = fmaf(xv, wv.z, acc[4*k+2]);
                    acc[4*k+3] = fmaf(xv, wv.w, acc[4*k+3]);
                }
            }
#pragma unroll
            for (int o = 0; o < C2d; ++o) mx[o] = fmaxf(mx[o], acc[o]);
        }
        if (sel == 0) {
            const int sw = idx & 7;
            float4* d4 = reinterpret_cast<float4*>(g_phi + (size_t)idx * C2d);
#pragma unroll
            for (int j = 0; j < 8; ++j)
                d4[j ^ sw] = make_float4(t32f(mx[4*j]), t32f(mx[4*j+1]),
                                         t32f(mx[4*j+2]), t32f(mx[4*j+3]));
        } else {
            // bf16, tile = 128 keys; physical row = key>>1 (128B), half = key&1
            uint4* base = g_gB4 + ((size_t)b * HW4 + (size_t)(m & ~127)) * 4;
            const int ml = m & 127, row = ml >> 1, half = ml & 1;
#pragma unroll
            for (int c = 0; c < 4; ++c) {
                uint4 v;
                v.x = pbf2(mx[8*c+0], mx[8*c+1]);
                v.y = pbf2(mx[8*c+2], mx[8*c+3]);
                v.z = pbf2(mx[8*c+4], mx[8*c+5]);
                v.w = pbf2(mx[8*c+6], mx[8*c+7]);
                int chunk = (half * 4 + c) ^ (row & 7);
                base[row * 8 + chunk] = v;
            }
        }
    }
}

// ===========================================================================
// Kernel 2: fully fused: theta-conv prologue + flash attention + out-conv
// epilogue (+residual). grid=(128,4), 256 thr.
// SMEM: Q 16K @0 | KV 2x24K @16384. Prologue reuses KV for x+w_theta;
// epilogue reuses KV for y, w_outT, b_out.
// ===========================================================================
#define OFF_Q    0
#define OFF_KV   16384
#define KVSTRIDE 24576
#define SMEM_AT  (16384 + 2 * 24576)

__global__ void __launch_bounds__(256, 2) attn_fused_kernel(
    const float* __restrict__ x,
    const float* __restrict__ w_theta, const float* __restrict__ b_theta,
    const float* __restrict__ w_out,   const float* __restrict__ b_out,
    float* __restrict__ out)
{
    extern __shared__ __align__(1024) char smem[];
    float* smf = reinterpret_cast<float*>(smem);
    const u32 sb = smem_u32(smem);
    const int tid = threadIdx.x, wid = tid >> 5, lane = tid & 31;
    const int b = blockIdx.y, q0 = blockIdx.x * 128;
    const float LOG2E = 1.44269504088896340736f;

    // ---------------- Prologue: theta = conv1x1(x, w_theta)+b, into Q smem ---
    {
        // stage x[b][c][q0..q0+128] -> smem [c][128] at OFF_KV (32 KB)
        const float* xs = x + (size_t)b * Cin * HW + q0;
#pragma unroll
        for (int i = 0; i < 8; ++i) {
            int idx = tid + 256 * i;           // 2048 chunks of 16B
            int c = idx >> 5, off = idx & 31;
            cp16(sb + OFF_KV + (u32)idx * 16, xs + (size_t)c * HW + off * 4);
        }
        cp_commit();
        // stage w_theta transposed [c][32] at OFF_KV+32768 (8 KB)
#pragma unroll
        for (int i = 0; i < 8; ++i) {
            int idx = tid + 256 * i;
            int c = idx >> 5, o = idx & 31;
            smf[(OFF_KV + 32768) / 4 + idx] = w_theta[o * Cin + c];
        }
        cp_wait<0>();
        __syncthreads();

        const int p = tid & 127, h = tid >> 7;     // pixel, out-half (16 o each)
        float acc[16];
#pragma unroll
        for (int j = 0; j < 16; ++j) acc[j] = __ldg(b_theta + h * 16 + j);
        const float* xs_s = smf + OFF_KV / 4;              // [c][128]
        const float* ws_s = smf + (OFF_KV + 32768) / 4;    // [c][32]
#pragma unroll 4
        for (int c = 0; c < Cin; ++c) {
            float xv = xs_s[c * 128 + p];
            const float4* wr = reinterpret_cast<const float4*>(ws_s + c * 32 + h * 16);
#pragma unroll
            for (int k = 0; k < 4; ++k) {
                float4 wv = wr[k];
                acc[4*k+0] = fmaf(xv, wv.x, acc[4*k+0]);
                acc[4*k+1] = fmaf(xv, wv.y, acc[4*k+1]);
                acc[4*k+2] = fmaf(xv, wv.z, acc[4*k+2]);
                acc[4*k+3] = fmaf(xv, wv.w, acc[4*k+3]);
            }
        }
        // store scaled+rounded theta into Q tile (swizzled rows)
#pragma unroll
        for (int ch = 0; ch < 4; ++ch) {
            u32 a = sb + OFF_Q + (u32)p * 128 + (u32)(((h * 4 + ch) ^ (p & 7)) * 16);
            sts128(a, to_tf32(acc[4*ch+0] * LOG2E), to_tf32(acc[4*ch+1] * LOG2E),
                      to_tf32(acc[4*ch+2] * LOG2E), to_tf32(acc[4*ch+3] * LOG2E));
        }
        __syncthreads();
    }

    // ---------------- KV pipeline ----------------
    auto load_kv = [&](int t, int bufi) {
        u32 d = sb + OFF_KV + (u32)bufi * KVSTRIDE;
        const char* sp = (const char*)(g_phi + (size_t)(b * HW4 + t * 128) * C2d);
#pragma unroll
        for (int i = 0; i < 4; ++i) {
            int idx = tid + 256 * i;
            cp16(d + (u32)idx * 16, sp + (size_t)idx * 16);
        }
        const char* sg = (const char*)(g_gB4 + ((size_t)b * HW4 + (size_t)t * 128) * 4);
#pragma unroll
        for (int i = 0; i < 2; ++i) {
            int idx = tid + 256 * i;
            cp16(d + 16384 + (u32)idx * 16, sg + (size_t)idx * 16);
        }
    };
    load_kv(0, 0);
    cp_commit();
    cp_wait<0>();
    __syncthreads();

    // Q A-frags (tf32, scaled by log2e)
    u32 qh[4][4];
#pragma unroll
    for (int ks = 0; ks < 4; ++ks) {
        u32 row = (u32)(16 * wid + ((lane >> 3) & 1) * 8 + (lane & 7));
        u32 chunk = (u32)(2 * ks + (lane >> 4));
        u32 a = sb + OFF_Q + row * 128 + ((chunk ^ (lane & 7u))) * 16;
        ldsm4(qh[ks][0], qh[ks][1], qh[ks][2], qh[ks][3], a);
    }

    float ofrag[4][4];
#pragma unroll
    for (int nb = 0; nb < 4; ++nb)
#pragma unroll
        for (int i = 0; i < 4; ++i) ofrag[nb][i] = 0.f;
    float rsum0 = 0.f, rsum1 = 0.f;

    const u32 Lm = (u32)(lane & 15);
    int buf = 0;

    for (int t = 0; t < NTI; ++t) {
        if (t + 1 < NTI) { load_kv(t + 1, buf ^ 1); cp_commit(); cp_wait<1>(); }
        else             { cp_wait<0>(); }
        __syncthreads();

        const u32 Koff = sb + OFF_KV + (u32)buf * KVSTRIDE;
        const u32 Goff = Koff + 16384;

#pragma unroll
        for (int jp = 0; jp < 8; ++jp) {
            const u32 kb = (u32)(jp * 16);
            float s0[4] = {0.f, 0.f, 0.f, 0.f}, s1[4] = {0.f, 0.f, 0.f, 0.f};
            const u32 kr0 = kb + (Lm & 7u), kr1 = kr0 + 8;
#pragma unroll
            for (int ks = 0; ks < 4; ++ks) {
                u32 ch = (u32)(2 * ks) + (Lm >> 3);
                u32 a0 = Koff + kr0 * 128 + ((ch ^ (kr0 & 7u))) * 16;
                u32 a1 = Koff + kr1 * 128 + ((ch ^ (kr1 & 7u))) * 16;
                u32 x0, x1, y0, y1;
                ldsm2(x0, x1, a0);
                ldsm2(y0, y1, a1);
                mma_tf32(s0, qh[ks], x0, x1);
                mma_tf32(s1, qh[ks], y0, y1);
            }
            float e00 = ex2f(s0[0]), e01 = ex2f(s0[1]);
            float e02 = ex2f(s0[2]), e03 = ex2f(s0[3]);
            float e10 = ex2f(s1[0]), e11 = ex2f(s1[1]);
            float e12 = ex2f(s1[2]), e13 = ex2f(s1[3]);
            rsum0 += (e00 + e01) + (e10 + e11);
            rsum1 += (e02 + e03) + (e12 + e13);
            u32 pa[4];
            pa[0] = pbf2(e00, e01);
            pa[1] = pbf2(e02, e03);
            pa[2] = pbf2(e10, e11);
            pa[3] = pbf2(e12, e13);
            const u32 key = kb + Lm;
            const u32 grow = key >> 1, ghalf = key & 1u;
#pragma unroll
            for (int nb = 0; nb < 4; ++nb) {
                u32 chunk = ((ghalf << 2) + (u32)nb) ^ (grow & 7u);
                u32 ga = Goff + grow * 128 + chunk * 16;
                u32 g0, g1;
                ldsm2t(g0, g1, ga);
                mma_bf16(ofrag[nb], pa, g0, g1);
            }
        }
        __syncthreads();
        buf ^= 1;
    }

    rsum0 += __shfl_xor_sync(0xFFFFFFFF, rsum0, 1);
    rsum0 += __shfl_xor_sync(0xFFFFFFFF, rsum0, 2);
    rsum1 += __shfl_xor_sync(0xFFFFFFFF, rsum1, 1);
    rsum1 += __shfl_xor_sync(0xFFFFFFFF, rsum1, 2);
    const float inv0 = 1.0f / rsum0, inv1 = 1.0f / rsum1;

    // ---------------- Epilogue: y -> smem, out = w_out^T y + b_out + x -------
    {
        // write normalized y into KV region (rows swizzled like Q)
        const u32 Yoff = sb + OFF_KV;
        const u32 r0l = (u32)(16 * wid + (lane >> 2));
        const u32 qq = (u32)(lane & 3);
#pragma unroll
        for (int nb = 0; nb < 4; ++nb) {
            u32 chunk = (u32)(2 * nb) + (qq >> 1);
            u32 a0 = Yoff + r0l * 128 + ((chunk ^ (r0l & 7u))) * 16 + (qq & 1u) * 8;
            sts64f(a0, ofrag[nb][0] * inv0, ofrag[nb][1] * inv0);
            u32 r1l = r0l + 8;
            u32 a1 = Yoff + r1l * 128 + ((chunk ^ (r1l & 7u))) * 16 + (qq & 1u) * 8;
            sts64f(a1, ofrag[nb][2] * inv1, ofrag[nb][3] * inv1);
        }
        // stage w_out transposed [c2][64] at OFF_KV+16384, b_out at +24576
#pragma unroll
        for (int i = 0; i < 8; ++i) {
            int idx = tid + 256 * i;
            int c2 = idx >> 6, o = idx & 63;
            smf[(OFF_KV + 16384) / 4 + idx] = w_out[o * C2d + c2];
        }
        if (tid < Cin) smf[(OFF_KV + 24576) / 4 + tid] = b_out[tid];
        __syncthreads();

        const int p = tid & 127, h = tid >> 7;   // pixel, out-half (32 o each)
        float yv[32];
#pragma unroll
        for (int ch = 0; ch < 8; ++ch) {
            u32 a = Yoff + (u32)p * 128 + (u32)((ch ^ (p & 7)) * 16);
            lds128f(yv[4*ch+0], yv[4*ch+1], yv[4*ch+2], yv[4*ch+3], a);
        }
        float acc[32];
        const float* bo = smf + (OFF_KV + 24576) / 4 + h * 32;
#pragma unroll
        for (int j = 0; j < 32; ++j) acc[j] = bo[j];
        const float* wT = smf + (OFF_KV + 16384) / 4;   // [c2][64]
#pragma unroll 4
        for (int c2 = 0; c2 < C2d; ++c2) {
            float yc = yv[c2];
            const float4* wr = reinterpret_cast<const float4*>(wT + c2 * 64 + h * 32);
#pragma unroll
            for (int k = 0; k < 8; ++k) {
                float4 wv = wr[k];
                acc[4*k+0] = fmaf(yc, wv.x, acc[4*k+0]);
                acc[4*k+1] = fmaf(yc, wv.y, acc[4*k+1]);
                acc[4*k+2] = fmaf(yc, wv.z, acc[4*k+2]);
                acc[4*k+3] = fmaf(yc, wv.w, acc[4*k+3]);
            }
        }
        const int n = q0 + p;
        const float* xb = x + (size_t)b * Cin * HW + n;
        float* ob = out + (size_t)b * Cin * HW + n;
#pragma unroll
        for (int j = 0; j < 32; ++j) {
            int o = h * 32 + j;
            ob[(size_t)o * HW] = acc[j] + xb[(size_t)o * HW];
        }
    }
}

// ===========================================================================
extern "C" void kernel_launch(void* const* d_in, const int* in_sizes, int n_in,
                              void* d_out, int out_size)
{
    const float* x       = (const float*)d_in[0];
    const float* w_theta = (const float*)d_in[1];
    const float* b_theta = (const float*)d_in[2];
    const float* w_phi   = (const float*)d_in[3];
    const float* b_phi   = (const float*)d_in[4];
    const float* w_g     = (const float*)d_in[5];
    const float* b_g     = (const float*)d_in[6];
    const float* w_out   = (const float*)d_in[7];
    const float* b_out   = (const float*)d_in[8];
    float* out = (float*)d_out;

    conv_pool_kernel<<<(Bsz * HW4) / 256, 256>>>(x, w_phi, b_phi, w_g, b_g);

    cudaFuncSetAttribute(attn_fused_kernel,
                         cudaFuncAttributeMaxDynamicSharedMemorySize, SMEM_AT);
    attn_fused_kernel<<<dim3(128, Bsz), 256, SMEM_AT>>>(
        x, w_theta, b_theta, w_out, b_out, out);
}

// round 8
// speedup vs baseline: 5.2178x; 1.1472x over previous
#include <cuda_runtime.h>
#include <cuda_bf16.h>
#include <cstdint>

#define Bsz   4
#define Cin   64
#define C2d   32
#define HW    16384
#define HW4   4096
#define NTI   32      // key tiles of 128

typedef unsigned int u32;

// Scratch (device globals)
__device__ __align__(1024) float g_phi [Bsz * HW4 * C2d];  // tf32-rounded fp32, swizzled rows [m][32]
__device__ __align__(1024) uint4 g_gB4 [Bsz * HW4 * 4];    // bf16, custom-swizzled 64B/key

// ---------------- helpers ----------------
__device__ __forceinline__ u32 smem_u32(const void* p) { return (u32)__cvta_generic_to_shared(p); }
__device__ __forceinline__ void cp16(u32 dst, const void* src) {
    asm volatile("cp.async.cg.shared.global [%0], [%1], 16;" :: "r"(dst), "l"(src));
}
__device__ __forceinline__ void cp_commit() { asm volatile("cp.async.commit_group;"); }
template <int N> __device__ __forceinline__ void cp_wait() {
    asm volatile("cp.async.wait_group %0;" :: "n"(N));
}
__device__ __forceinline__ void ldsm4(u32& r0, u32& r1, u32& r2, u32& r3, u32 a) {
    asm volatile("ldmatrix.sync.aligned.m8n8.x4.shared.b16 {%0,%1,%2,%3}, [%4];"
                 : "=r"(r0), "=r"(r1), "=r"(r2), "=r"(r3) : "r"(a));
}
__device__ __forceinline__ void ldsm4t(u32& r0, u32& r1, u32& r2, u32& r3, u32 a) {
    asm volatile("ldmatrix.sync.aligned.m8n8.x4.trans.shared.b16 {%0,%1,%2,%3}, [%4];"
                 : "=r"(r0), "=r"(r1), "=r"(r2), "=r"(r3) : "r"(a));
}
__device__ __forceinline__ u32 to_tf32(float f) {
    u32 r; asm("cvt.rna.tf32.f32 %0, %1;" : "=r"(r) : "f"(f)); return r;
}
__device__ __forceinline__ float t32f(float f) { return __uint_as_float(to_tf32(f)); }
__device__ __forceinline__ u32 pbf2(float lo, float hi) {
    u32 r; asm("cvt.rn.bf16x2.f32 %0, %1, %2;" : "=r"(r) : "f"(hi), "f"(lo)); return r;
}
__device__ __forceinline__ float ex2f(float x) {
    float r; asm("ex2.approx.f32 %0, %1;" : "=f"(r) : "f"(x)); return r;
}
__device__ __forceinline__ void sts128(u32 a, u32 c0, u32 c1, u32 c2, u32 c3) {
    asm volatile("st.shared.v4.b32 [%0], {%1,%2,%3,%4};"
                 :: "r"(a), "r"(c0), "r"(c1), "r"(c2), "r"(c3) : "memory");
}
__device__ __forceinline__ void sts64f(u32 a, float x, float y) {
    asm volatile("st.shared.v2.f32 [%0], {%1,%2};" :: "r"(a), "f"(x), "f"(y) : "memory");
}
__device__ __forceinline__ void lds128f(float& a, float& b, float& c, float& d, u32 addr) {
    asm volatile("ld.shared.v4.f32 {%0,%1,%2,%3}, [%4];"
                 : "=f"(a), "=f"(b), "=f"(c), "=f"(d) : "r"(addr));
}
__device__ __forceinline__ void mma_tf32(float* c, const u32* a, u32 b0, u32 b1) {
    asm volatile("mma.sync.aligned.m16n8k8.row.col.f32.tf32.tf32.f32 "
                 "{%0,%1,%2,%3}, {%4,%5,%6,%7}, {%8,%9}, {%0,%1,%2,%3};"
                 : "+f"(c[0]), "+f"(c[1]), "+f"(c[2]), "+f"(c[3])
                 : "r"(a[0]), "r"(a[1]), "r"(a[2]), "r"(a[3]), "r"(b0), "r"(b1));
}
__device__ __forceinline__ void mma_bf16(float* c, const u32* a, u32 b0, u32 b1) {
    asm volatile("mma.sync.aligned.m16n8k16.row.col.f32.bf16.bf16.f32 "
                 "{%0,%1,%2,%3}, {%4,%5,%6,%7}, {%8,%9}, {%0,%1,%2,%3};"
                 : "+f"(c[0]), "+f"(c[1]), "+f"(c[2]), "+f"(c[3])
                 : "r"(a[0]), "r"(a[1]), "r"(a[2]), "r"(a[3]), "r"(b0), "r"(b1));
}

// ===========================================================================
// Kernel 1: phi (tf32-rounded, swizzled rows) & g (bf16 custom-swizzled)
// blockIdx.y selects which conv (0=phi, 1=g) -> 2x parallelism
// ===========================================================================
__global__ void __launch_bounds__(256) conv_pool_kernel(
    const float* __restrict__ x,
    const float* __restrict__ wphi, const float* __restrict__ bphi,
    const float* __restrict__ wg,   const float* __restrict__ bg)
{
    __shared__ float ws[Cin * C2d];
    __shared__ float bs[C2d];
    const int tid = threadIdx.x;
    const int sel = blockIdx.y;
    const float* wsrc = sel ? wg : wphi;
    const float* bsrc = sel ? bg : bphi;
    for (int i = tid; i < Cin * C2d; i += 256) {
        int c = i >> 5, o = i & 31;
        ws[i] = wsrc[o * Cin + c];
    }
    if (tid < C2d) bs[tid] = bsrc[tid];
    __syncthreads();

    const int idx = blockIdx.x * 256 + tid;
    const int b = idx >> 12, m = idx & (HW4 - 1);
    const int h2 = m >> 6, w2i = m & 63;
    const float* xb = x + (size_t)b * Cin * HW;

    float mx[C2d];
#pragma unroll
    for (int o = 0; o < C2d; ++o) mx[o] = -3.0e38f;
    const float4* ws4 = reinterpret_cast<const float4*>(ws);
#pragma unroll 1
    for (int px = 0; px < 4; ++px) {
        const int n = (2 * h2 + (px >> 1)) * 128 + 2 * w2i + (px & 1);
        float acc[C2d];
#pragma unroll
        for (int o = 0; o < C2d; ++o) acc[o] = bs[o];
        for (int c = 0; c < Cin; ++c) {
            float xv = xb[(size_t)c * HW + n];
#pragma unroll
            for (int k = 0; k < 8; ++k) {
                float4 wv = ws4[c * 8 + k];
                acc[4*k+0] = fmaf(xv, wv.x, acc[4*k+0]);
                acc[4*k+1] = fmaf(xv, wv.y, acc[4*k+1]);
                acc[4*k+2] = fmaf(xv, wv.z, acc[4*k+2]);
                acc[4*k+3] = fmaf(xv, wv.w, acc[4*k+3]);
            }
        }
#pragma unroll
        for (int o = 0; o < C2d; ++o) mx[o] = fmaxf(mx[o], acc[o]);
    }
    if (sel == 0) {
        const int sw = idx & 7;
        float4* d4 = reinterpret_cast<float4*>(g_phi + (size_t)idx * C2d);
#pragma unroll
        for (int j = 0; j < 8; ++j)
            d4[j ^ sw] = make_float4(t32f(mx[4*j]), t32f(mx[4*j+1]),
                                     t32f(mx[4*j+2]), t32f(mx[4*j+3]));
    } else {
        uint4* base = g_gB4 + ((size_t)b * HW4 + (size_t)(m & ~127)) * 4;
        const int ml = m & 127, row = ml >> 1, half = ml & 1;
#pragma unroll
        for (int c = 0; c < 4; ++c) {
            uint4 v;
            v.x = pbf2(mx[8*c+0], mx[8*c+1]);
            v.y = pbf2(mx[8*c+2], mx[8*c+3]);
            v.z = pbf2(mx[8*c+4], mx[8*c+5]);
            v.w = pbf2(mx[8*c+6], mx[8*c+7]);
            int chunk = (half * 4 + c) ^ (row & 7);
            base[row * 8 + chunk] = v;
        }
    }
}

// ===========================================================================
// Kernel 2: fused theta-conv + flash attention + out-conv (+residual).
// grid=(128,4), 128 thr (4 warps), each warp m32 x all 128 keys per tile.
// SMEM: Q 16K @0 | KV 2x24K @16384 = 64 KB; 3 CTAs/SM.
// ===========================================================================
#define OFF_Q    0
#define OFF_KV   16384
#define KVSTRIDE 24576
#define SMEM_AT  (16384 + 2 * 24576)

__global__ void __launch_bounds__(128, 3) attn_fused_kernel(
    const float* __restrict__ x,
    const float* __restrict__ w_theta, const float* __restrict__ b_theta,
    const float* __restrict__ w_out,   const float* __restrict__ b_out,
    float* __restrict__ out)
{
    extern __shared__ __align__(1024) char smem[];
    float* smf = reinterpret_cast<float*>(smem);
    const u32 sb = smem_u32(smem);
    const int tid = threadIdx.x, wid = tid >> 5, lane = tid & 31;
    const int b = blockIdx.y, q0 = blockIdx.x * 128;
    const float LOG2E = 1.44269504088896340736f;

    // ---------------- Prologue: theta into Q smem ----------------
    {
        const float* xs = x + (size_t)b * Cin * HW + q0;
#pragma unroll
        for (int i = 0; i < 16; ++i) {
            int idx = tid + 128 * i;           // 2048 chunks of 16B
            int c = idx >> 5, off = idx & 31;
            cp16(sb + OFF_KV + (u32)idx * 16, xs + (size_t)c * HW + off * 4);
        }
        cp_commit();
#pragma unroll
        for (int i = 0; i < 16; ++i) {
            int idx = tid + 128 * i;
            int c = idx >> 5, o = idx & 31;
            smf[(OFF_KV + 32768) / 4 + idx] = w_theta[o * Cin + c];
        }
        cp_wait<0>();
        __syncthreads();

        const int p = tid;                       // pixel, all 32 outs
        float acc[C2d];
#pragma unroll
        for (int j = 0; j < C2d; ++j) acc[j] = __ldg(b_theta + j);
        const float* xs_s = smf + OFF_KV / 4;              // [c][128]
        const float* ws_s = smf + (OFF_KV + 32768) / 4;    // [c][32]
#pragma unroll 4
        for (int c = 0; c < Cin; ++c) {
            float xv = xs_s[c * 128 + p];
            const float4* wr = reinterpret_cast<const float4*>(ws_s + c * 32);
#pragma unroll
            for (int k = 0; k < 8; ++k) {
                float4 wv = wr[k];
                acc[4*k+0] = fmaf(xv, wv.x, acc[4*k+0]);
                acc[4*k+1] = fmaf(xv, wv.y, acc[4*k+1]);
                acc[4*k+2] = fmaf(xv, wv.z, acc[4*k+2]);
                acc[4*k+3] = fmaf(xv, wv.w, acc[4*k+3]);
            }
        }
#pragma unroll
        for (int ch = 0; ch < 8; ++ch) {
            u32 a = sb + OFF_Q + (u32)p * 128 + (u32)((ch ^ (p & 7)) * 16);
            sts128(a, to_tf32(acc[4*ch+0] * LOG2E), to_tf32(acc[4*ch+1] * LOG2E),
                      to_tf32(acc[4*ch+2] * LOG2E), to_tf32(acc[4*ch+3] * LOG2E));
        }
        __syncthreads();
    }

    // ---------------- KV pipeline ----------------
    auto load_kv = [&](int t, int bufi) {
        u32 d = sb + OFF_KV + (u32)bufi * KVSTRIDE;
        const char* sp = (const char*)(g_phi + (size_t)(b * HW4 + t * 128) * C2d);
#pragma unroll
        for (int i = 0; i < 8; ++i) {
            int idx = tid + 128 * i;
            cp16(d + (u32)idx * 16, sp + (size_t)idx * 16);
        }
        const char* sg = (const char*)(g_gB4 + ((size_t)b * HW4 + (size_t)t * 128) * 4);
#pragma unroll
        for (int i = 0; i < 4; ++i) {
            int idx = tid + 128 * i;
            cp16(d + 16384 + (u32)idx * 16, sg + (size_t)idx * 16);
        }
    };
    load_kv(0, 0);
    cp_commit();
    cp_wait<0>();
    __syncthreads();

    // Q A-frags: 2 q-subblocks of m16 per warp
    u32 qh[2][4][4];
#pragma unroll
    for (int qb = 0; qb < 2; ++qb)
#pragma unroll
    for (int ks = 0; ks < 4; ++ks) {
        u32 row = (u32)(32 * wid + 16 * qb + ((lane >> 3) & 1) * 8 + (lane & 7));
        u32 chunk = (u32)(2 * ks + (lane >> 4));
        u32 a = sb + OFF_Q + row * 128 + ((chunk ^ (lane & 7u))) * 16;
        ldsm4(qh[qb][ks][0], qh[qb][ks][1], qh[qb][ks][2], qh[qb][ks][3], a);
    }

    float ofrag[2][4][4];
#pragma unroll
    for (int qb = 0; qb < 2; ++qb)
#pragma unroll
    for (int nb = 0; nb < 4; ++nb)
#pragma unroll
        for (int i = 0; i < 4; ++i) ofrag[qb][nb][i] = 0.f;
    float rsum[2][2] = {{0.f, 0.f}, {0.f, 0.f}};

    int buf = 0;
    for (int t = 0; t < NTI; ++t) {
        if (t + 1 < NTI) { load_kv(t + 1, buf ^ 1); cp_commit(); cp_wait<1>(); }
        else             { cp_wait<0>(); }
        __syncthreads();

        const u32 Koff = sb + OFF_KV + (u32)buf * KVSTRIDE;
        const u32 Goff = Koff + 16384;

#pragma unroll
        for (int jp = 0; jp < 8; ++jp) {
            const u32 kb = (u32)(jp * 16);
            float s[2][2][4];
#pragma unroll
            for (int qb = 0; qb < 2; ++qb)
#pragma unroll
                for (int blk = 0; blk < 2; ++blk)
#pragma unroll
                    for (int i = 0; i < 4; ++i) s[qb][blk][i] = 0.f;

            // K frags via x4: mats = (blk0,ch0),(blk0,ch1),(blk1,ch0),(blk1,ch1)
            const u32 krow = kb + (u32)(((lane >> 4) << 3) + (lane & 7));
#pragma unroll
            for (int ks = 0; ks < 4; ++ks) {
                u32 ch = (u32)(2 * ks) + ((u32)(lane >> 3) & 1u);
                u32 a = Koff + krow * 128 + ((ch ^ (lane & 7u))) * 16;
                u32 x0, x1, y0, y1;
                ldsm4(x0, x1, y0, y1, a);
                mma_tf32(s[0][0], qh[0][ks], x0, x1);
                mma_tf32(s[1][0], qh[1][ks], x0, x1);
                mma_tf32(s[0][1], qh[0][ks], y0, y1);
                mma_tf32(s[1][1], qh[1][ks], y0, y1);
            }

            u32 pa[2][4];
#pragma unroll
            for (int qb = 0; qb < 2; ++qb) {
                float e00 = ex2f(s[qb][0][0]), e01 = ex2f(s[qb][0][1]);
                float e02 = ex2f(s[qb][0][2]), e03 = ex2f(s[qb][0][3]);
                float e10 = ex2f(s[qb][1][0]), e11 = ex2f(s[qb][1][1]);
                float e12 = ex2f(s[qb][1][2]), e13 = ex2f(s[qb][1][3]);
                rsum[qb][0] += (e00 + e01) + (e10 + e11);
                rsum[qb][1] += (e02 + e03) + (e12 + e13);
                pa[qb][0] = pbf2(e00, e01);
                pa[qb][1] = pbf2(e02, e03);
                pa[qb][2] = pbf2(e10, e11);
                pa[qb][3] = pbf2(e12, e13);
            }

            // G frags via x4 trans: mats = (nbb,g0),(nbb,g1),(nbb+1,g0),(nbb+1,g1)
            const u32 key = kb + (u32)(lane & 15);
            const u32 grow = key >> 1, ghalf = key & 1u;
            const u32 nbhi = (u32)(lane >> 4);
#pragma unroll
            for (int nbb = 0; nbb < 4; nbb += 2) {
                u32 nbp = (u32)nbb + nbhi;
                u32 chunk = ((ghalf << 2) + nbp) ^ (grow & 7u);
                u32 ga = Goff + grow * 128 + chunk * 16;
                u32 g00, g01, g10, g11;
                ldsm4t(g00, g01, g10, g11, ga);
                mma_bf16(ofrag[0][nbb],     pa[0], g00, g01);
                mma_bf16(ofrag[1][nbb],     pa[1], g00, g01);
                mma_bf16(ofrag[0][nbb + 1], pa[0], g10, g11);
                mma_bf16(ofrag[1][nbb + 1], pa[1], g10, g11);
            }
        }
        __syncthreads();
        buf ^= 1;
    }

    float inv[2][2];
#pragma unroll
    for (int qb = 0; qb < 2; ++qb)
#pragma unroll
        for (int hh = 0; hh < 2; ++hh) {
            float r = rsum[qb][hh];
            r += __shfl_xor_sync(0xFFFFFFFF, r, 1);
            r += __shfl_xor_sync(0xFFFFFFFF, r, 2);
            inv[qb][hh] = 1.0f / r;
        }

    // ---------------- Epilogue: y -> smem, out = w_out^T y + b_out + x -------
    {
        const u32 Yoff = sb + OFF_KV;
        const u32 qq = (u32)(lane & 3);
#pragma unroll
        for (int qb = 0; qb < 2; ++qb) {
            const u32 r0l = (u32)(32 * wid + 16 * qb + (lane >> 2));
#pragma unroll
            for (int nb = 0; nb < 4; ++nb) {
                u32 chunk = (u32)(2 * nb) + (qq >> 1);
                u32 a0 = Yoff + r0l * 128 + ((chunk ^ (r0l & 7u))) * 16 + (qq & 1u) * 8;
                sts64f(a0, ofrag[qb][nb][0] * inv[qb][0], ofrag[qb][nb][1] * inv[qb][0]);
                u32 r1l = r0l + 8;
                u32 a1 = Yoff + r1l * 128 + ((chunk ^ (r1l & 7u))) * 16 + (qq & 1u) * 8;
                sts64f(a1, ofrag[qb][nb][2] * inv[qb][1], ofrag[qb][nb][3] * inv[qb][1]);
            }
        }
        // stage w_out transposed [c2][64] at OFF_KV+16384, b_out at +24576
#pragma unroll
        for (int i = 0; i < 16; ++i) {
            int idx = tid + 128 * i;
            int c2 = idx >> 6, o = idx & 63;
            smf[(OFF_KV + 16384) / 4 + idx] = w_out[o * C2d + c2];
        }
        if (tid < Cin) smf[(OFF_KV + 24576) / 4 + tid] = b_out[tid];
        __syncthreads();

        const int p = tid;
        float yv[32];
#pragma unroll
        for (int ch = 0; ch < 8; ++ch) {
            u32 a = Yoff + (u32)p * 128 + (u32)((ch ^ (p & 7)) * 16);
            lds128f(yv[4*ch+0], yv[4*ch+1], yv[4*ch+2], yv[4*ch+3], a);
        }
        const float* wT = smf + (OFF_KV + 16384) / 4;   // [c2][64]
        const float* bo = smf + (OFF_KV + 24576) / 4;
        const int n = q0 + p;
        const float* xb = x + (size_t)b * Cin * HW + n;
        float* ob = out + (size_t)b * Cin * HW + n;
#pragma unroll 1
        for (int h = 0; h < 2; ++h) {
            float acc[32];
#pragma unroll
            for (int j = 0; j < 32; ++j) acc[j] = bo[h * 32 + j];
#pragma unroll 4
            for (int c2 = 0; c2 < C2d; ++c2) {
                float yc = yv[c2];
                const float4* wr = reinterpret_cast<const float4*>(wT + c2 * 64 + h * 32);
#pragma unroll
                for (int k = 0; k < 8; ++k) {
                    float4 wv = wr[k];
                    acc[4*k+0] = fmaf(yc, wv.x, acc[4*k+0]);
                    acc[4*k+1] = fmaf(yc, wv.y, acc[4*k+1]);
                    acc[4*k+2] = fmaf(yc, wv.z, acc[4*k+2]);
                    acc[4*k+3] = fmaf(yc, wv.w, acc[4*k+3]);
                }
            }
#pragma unroll
            for (int j = 0; j < 32; ++j) {
                int o = h * 32 + j;
                ob[(size_t)o * HW] = acc[j] + xb[(size_t)o * HW];
            }
        }
    }
}

// ===========================================================================
extern "C" void kernel_launch(void* const* d_in, const int* in_sizes, int n_in,
                              void* d_out, int out_size)
{
    const float* x       = (const float*)d_in[0];
    const float* w_theta = (const float*)d_in[1];
    const float* b_theta = (const float*)d_in[2];
    const float* w_phi   = (const float*)d_in[3];
    const float* b_phi   = (const float*)d_in[4];
    const float* w_g     = (const float*)d_in[5];
    const float* b_g     = (const float*)d_in[6];
    const float* w_out   = (const float*)d_in[7];
    const float* b_out   = (const float*)d_in[8];
    float* out = (float*)d_out;

    conv_pool_kernel<<<dim3((Bsz * HW4) / 256, 2), 256>>>(x, w_phi, b_phi, w_g, b_g);

    cudaFuncSetAttribute(attn_fused_kernel,
                         cudaFuncAttributeMaxDynamicSharedMemorySize, SMEM_AT);
    attn_fused_kernel<<<dim3(128, Bsz), 128, SMEM_AT>>>(
        x, w_theta, b_theta, w_out, b_out, out);
}

// round 9
// speedup vs baseline: 5.6708x; 1.0868x over previous
#include <cuda_runtime.h>
#include <cuda_bf16.h>
#include <cstdint>

#define Bsz   4
#define Cin   64
#define C2d   32
#define HW    16384
#define HW4   4096
#define NTI   32      // key tiles of 128
#define NSPL  2       // key splits

typedef unsigned int u32;

// Scratch (device globals)
__device__ __align__(1024) float g_phi [Bsz * HW4 * C2d];      // tf32-rounded, swizzled rows
__device__ __align__(1024) uint4 g_gB4 [Bsz * HW4 * 4];        // bf16, custom-swizzled
__device__ __align__(1024) float g_yp  [NSPL * Bsz * HW * C2d];// unnormalized y partials
__device__ __align__(1024) float g_rs  [NSPL * Bsz * HW];      // partial row sums

// ---------------- helpers ----------------
__device__ __forceinline__ u32 smem_u32(const void* p) { return (u32)__cvta_generic_to_shared(p); }
__device__ __forceinline__ void cp16(u32 dst, const void* src) {
    asm volatile("cp.async.cg.shared.global [%0], [%1], 16;" :: "r"(dst), "l"(src));
}
__device__ __forceinline__ void cp_commit() { asm volatile("cp.async.commit_group;"); }
template <int N> __device__ __forceinline__ void cp_wait() {
    asm volatile("cp.async.wait_group %0;" :: "n"(N));
}
__device__ __forceinline__ void ldsm4(u32& r0, u32& r1, u32& r2, u32& r3, u32 a) {
    asm volatile("ldmatrix.sync.aligned.m8n8.x4.shared.b16 {%0,%1,%2,%3}, [%4];"
                 : "=r"(r0), "=r"(r1), "=r"(r2), "=r"(r3) : "r"(a));
}
__device__ __forceinline__ void ldsm4t(u32& r0, u32& r1, u32& r2, u32& r3, u32 a) {
    asm volatile("ldmatrix.sync.aligned.m8n8.x4.trans.shared.b16 {%0,%1,%2,%3}, [%4];"
                 : "=r"(r0), "=r"(r1), "=r"(r2), "=r"(r3) : "r"(a));
}
__device__ __forceinline__ u32 to_tf32(float f) {
    u32 r; asm("cvt.rna.tf32.f32 %0, %1;" : "=r"(r) : "f"(f)); return r;
}
__device__ __forceinline__ float t32f(float f) { return __uint_as_float(to_tf32(f)); }
__device__ __forceinline__ u32 pbf2(float lo, float hi) {
    u32 r; asm("cvt.rn.bf16x2.f32 %0, %1, %2;" : "=r"(r) : "f"(hi), "f"(lo)); return r;
}
__device__ __forceinline__ float ex2f(float x) {
    float r; asm("ex2.approx.f32 %0, %1;" : "=f"(r) : "f"(x)); return r;
}
__device__ __forceinline__ void sts128(u32 a, u32 c0, u32 c1, u32 c2, u32 c3) {
    asm volatile("st.shared.v4.b32 [%0], {%1,%2,%3,%4};"
                 :: "r"(a), "r"(c0), "r"(c1), "r"(c2), "r"(c3) : "memory");
}
__device__ __forceinline__ void mma_tf32(float* c, const u32* a, u32 b0, u32 b1) {
    asm volatile("mma.sync.aligned.m16n8k8.row.col.f32.tf32.tf32.f32 "
                 "{%0,%1,%2,%3}, {%4,%5,%6,%7}, {%8,%9}, {%0,%1,%2,%3};"
                 : "+f"(c[0]), "+f"(c[1]), "+f"(c[2]), "+f"(c[3])
                 : "r"(a[0]), "r"(a[1]), "r"(a[2]), "r"(a[3]), "r"(b0), "r"(b1));
}
__device__ __forceinline__ void mma_bf16(float* c, const u32* a, u32 b0, u32 b1) {
    asm volatile("mma.sync.aligned.m16n8k16.row.col.f32.bf16.bf16.f32 "
                 "{%0,%1,%2,%3}, {%4,%5,%6,%7}, {%8,%9}, {%0,%1,%2,%3};"
                 : "+f"(c[0]), "+f"(c[1]), "+f"(c[2]), "+f"(c[3])
                 : "r"(a[0]), "r"(a[1]), "r"(a[2]), "r"(a[3]), "r"(b0), "r"(b1));
}

// ===========================================================================
// Kernel 1: phi & g producers; blockIdx.y = which conv, 128-thr blocks
// ===========================================================================
__global__ void __launch_bounds__(128) conv_pool_kernel(
    const float* __restrict__ x,
    const float* __restrict__ wphi, const float* __restrict__ bphi,
    const float* __restrict__ wg,   const float* __restrict__ bg)
{
    __shared__ float ws[Cin * C2d];
    __shared__ float bs[C2d];
    const int tid = threadIdx.x;
    const int sel = blockIdx.y;
    const float* wsrc = sel ? wg : wphi;
    const float* bsrc = sel ? bg : bphi;
    for (int i = tid; i < Cin * C2d; i += 128) {
        int c = i >> 5, o = i & 31;
        ws[i] = wsrc[o * Cin + c];
    }
    if (tid < C2d) bs[tid] = bsrc[tid];
    __syncthreads();

    const int idx = blockIdx.x * 128 + tid;
    const int b = idx >> 12, m = idx & (HW4 - 1);
    const int h2 = m >> 6, w2i = m & 63;
    const float* xb = x + (size_t)b * Cin * HW;

    float mx[C2d];
#pragma unroll
    for (int o = 0; o < C2d; ++o) mx[o] = -3.0e38f;
    const float4* ws4 = reinterpret_cast<const float4*>(ws);
#pragma unroll 1
    for (int px = 0; px < 4; ++px) {
        const int n = (2 * h2 + (px >> 1)) * 128 + 2 * w2i + (px & 1);
        float acc[C2d];
#pragma unroll
        for (int o = 0; o < C2d; ++o) acc[o] = bs[o];
        for (int c = 0; c < Cin; ++c) {
            float xv = xb[(size_t)c * HW + n];
#pragma unroll
            for (int k = 0; k < 8; ++k) {
                float4 wv = ws4[c * 8 + k];
                acc[4*k+0] = fmaf(xv, wv.x, acc[4*k+0]);
                acc[4*k+1] = fmaf(xv, wv.y, acc[4*k+1]);
                acc[4*k+2] = fmaf(xv, wv.z, acc[4*k+2]);
                acc[4*k+3] = fmaf(xv, wv.w, acc[4*k+3]);
            }
        }
#pragma unroll
        for (int o = 0; o < C2d; ++o) mx[o] = fmaxf(mx[o], acc[o]);
    }
    if (sel == 0) {
        const int sw = idx & 7;
        float4* d4 = reinterpret_cast<float4*>(g_phi + (size_t)idx * C2d);
#pragma unroll
        for (int j = 0; j < 8; ++j)
            d4[j ^ sw] = make_float4(t32f(mx[4*j]), t32f(mx[4*j+1]),
                                     t32f(mx[4*j+2]), t32f(mx[4*j+3]));
    } else {
        uint4* base = g_gB4 + ((size_t)b * HW4 + (size_t)(m & ~127)) * 4;
        const int ml = m & 127, row = ml >> 1, half = ml & 1;
#pragma unroll
        for (int c = 0; c < 4; ++c) {
            uint4 v;
            v.x = pbf2(mx[8*c+0], mx[8*c+1]);
            v.y = pbf2(mx[8*c+2], mx[8*c+3]);
            v.z = pbf2(mx[8*c+4], mx[8*c+5]);
            v.w = pbf2(mx[8*c+6], mx[8*c+7]);
            int chunk = (half * 4 + c) ^ (row & 7);
            base[row * 8 + chunk] = v;
        }
    }
}

// ===========================================================================
// Kernel 2: fused theta-conv + flash attention, 2-way key split.
// grid=(128,4,2), 128 thr (4 warps x m32). Writes unnormalized partials.
// SMEM: Q 16K @0 | KV 2x24K @16384 = 64 KB; 3 CTAs/SM.
// ===========================================================================
#define OFF_Q    0
#define OFF_KV   16384
#define KVSTRIDE 24576
#define SMEM_AT  (16384 + 2 * 24576)

__global__ void __launch_bounds__(128, 3) attn_fused_kernel(
    const float* __restrict__ x,
    const float* __restrict__ w_theta, const float* __restrict__ b_theta)
{
    extern __shared__ __align__(1024) char smem[];
    float* smf = reinterpret_cast<float*>(smem);
    const u32 sb = smem_u32(smem);
    const int tid = threadIdx.x, wid = tid >> 5, lane = tid & 31;
    const int b = blockIdx.y, q0 = blockIdx.x * 128;
    const int split = blockIdx.z;
    const int t0 = split * (NTI / NSPL), t1 = t0 + NTI / NSPL;
    const float LOG2E = 1.44269504088896340736f;

    // ---------------- Prologue: theta into Q smem ----------------
    {
        const float* xs = x + (size_t)b * Cin * HW + q0;
#pragma unroll
        for (int i = 0; i < 16; ++i) {
            int idx = tid + 128 * i;
            int c = idx >> 5, off = idx & 31;
            cp16(sb + OFF_KV + (u32)idx * 16, xs + (size_t)c * HW + off * 4);
        }
        cp_commit();
#pragma unroll
        for (int i = 0; i < 16; ++i) {
            int idx = tid + 128 * i;
            int c = idx >> 5, o = idx & 31;
            smf[(OFF_KV + 32768) / 4 + idx] = w_theta[o * Cin + c];
        }
        cp_wait<0>();
        __syncthreads();

        const int p = tid;
        float acc[C2d];
#pragma unroll
        for (int j = 0; j < C2d; ++j) acc[j] = __ldg(b_theta + j);
        const float* xs_s = smf + OFF_KV / 4;
        const float* ws_s = smf + (OFF_KV + 32768) / 4;
#pragma unroll 4
        for (int c = 0; c < Cin; ++c) {
            float xv = xs_s[c * 128 + p];
            const float4* wr = reinterpret_cast<const float4*>(ws_s + c * 32);
#pragma unroll
            for (int k = 0; k < 8; ++k) {
                float4 wv = wr[k];
                acc[4*k+0] = fmaf(xv, wv.x, acc[4*k+0]);
                acc[4*k+1] = fmaf(xv, wv.y, acc[4*k+1]);
                acc[4*k+2] = fmaf(xv, wv.z, acc[4*k+2]);
                acc[4*k+3] = fmaf(xv, wv.w, acc[4*k+3]);
            }
        }
#pragma unroll
        for (int ch = 0; ch < 8; ++ch) {
            u32 a = sb + OFF_Q + (u32)p * 128 + (u32)((ch ^ (p & 7)) * 16);
            sts128(a, to_tf32(acc[4*ch+0] * LOG2E), to_tf32(acc[4*ch+1] * LOG2E),
                      to_tf32(acc[4*ch+2] * LOG2E), to_tf32(acc[4*ch+3] * LOG2E));
        }
        __syncthreads();
    }

    // ---------------- KV pipeline ----------------
    auto load_kv = [&](int t, int bufi) {
        u32 d = sb + OFF_KV + (u32)bufi * KVSTRIDE;
        const char* sp = (const char*)(g_phi + (size_t)(b * HW4 + t * 128) * C2d);
#pragma unroll
        for (int i = 0; i < 8; ++i) {
            int idx = tid + 128 * i;
            cp16(d + (u32)idx * 16, sp + (size_t)idx * 16);
        }
        const char* sg = (const char*)(g_gB4 + ((size_t)b * HW4 + (size_t)t * 128) * 4);
#pragma unroll
        for (int i = 0; i < 4; ++i) {
            int idx = tid + 128 * i;
            cp16(d + 16384 + (u32)idx * 16, sg + (size_t)idx * 16);
        }
    };
    load_kv(t0, 0);
    cp_commit();
    cp_wait<0>();
    __syncthreads();

    // Q A-frags: 2 q-subblocks of m16 per warp
    u32 qh[2][4][4];
#pragma unroll
    for (int qb = 0; qb < 2; ++qb)
#pragma unroll
    for (int ks = 0; ks < 4; ++ks) {
        u32 row = (u32)(32 * wid + 16 * qb + ((lane >> 3) & 1) * 8 + (lane & 7));
        u32 chunk = (u32)(2 * ks + (lane >> 4));
        u32 a = sb + OFF_Q + row * 128 + ((chunk ^ (lane & 7u))) * 16;
        ldsm4(qh[qb][ks][0], qh[qb][ks][1], qh[qb][ks][2], qh[qb][ks][3], a);
    }

    float ofrag[2][4][4];
#pragma unroll
    for (int qb = 0; qb < 2; ++qb)
#pragma unroll
    for (int nb = 0; nb < 4; ++nb)
#pragma unroll
        for (int i = 0; i < 4; ++i) ofrag[qb][nb][i] = 0.f;
    float rsum[2][2] = {{0.f, 0.f}, {0.f, 0.f}};

    int buf = 0;
    for (int t = t0; t < t1; ++t) {
        if (t + 1 < t1) { load_kv(t + 1, buf ^ 1); cp_commit(); cp_wait<1>(); }
        else            { cp_wait<0>(); }
        __syncthreads();

        const u32 Koff = sb + OFF_KV + (u32)buf * KVSTRIDE;
        const u32 Goff = Koff + 16384;

#pragma unroll
        for (int jp = 0; jp < 8; ++jp) {
            const u32 kb = (u32)(jp * 16);
            float s[2][2][4];
#pragma unroll
            for (int qb = 0; qb < 2; ++qb)
#pragma unroll
                for (int blk = 0; blk < 2; ++blk)
#pragma unroll
                    for (int i = 0; i < 4; ++i) s[qb][blk][i] = 0.f;

            const u32 krow = kb + (u32)(((lane >> 4) << 3) + (lane & 7));
#pragma unroll
            for (int ks = 0; ks < 4; ++ks) {
                u32 ch = (u32)(2 * ks) + ((u32)(lane >> 3) & 1u);
                u32 a = Koff + krow * 128 + ((ch ^ (lane & 7u))) * 16;
                u32 x0, x1, y0, y1;
                ldsm4(x0, x1, y0, y1, a);
                mma_tf32(s[0][0], qh[0][ks], x0, x1);
                mma_tf32(s[1][0], qh[1][ks], x0, x1);
                mma_tf32(s[0][1], qh[0][ks], y0, y1);
                mma_tf32(s[1][1], qh[1][ks], y0, y1);
            }

            u32 pa[2][4];
#pragma unroll
            for (int qb = 0; qb < 2; ++qb) {
                float e00 = ex2f(s[qb][0][0]), e01 = ex2f(s[qb][0][1]);
                float e02 = ex2f(s[qb][0][2]), e03 = ex2f(s[qb][0][3]);
                float e10 = ex2f(s[qb][1][0]), e11 = ex2f(s[qb][1][1]);
                float e12 = ex2f(s[qb][1][2]), e13 = ex2f(s[qb][1][3]);
                rsum[qb][0] += (e00 + e01) + (e10 + e11);
                rsum[qb][1] += (e02 + e03) + (e12 + e13);
                pa[qb][0] = pbf2(e00, e01);
                pa[qb][1] = pbf2(e02, e03);
                pa[qb][2] = pbf2(e10, e11);
                pa[qb][3] = pbf2(e12, e13);
            }

            const u32 key = kb + (u32)(lane & 15);
            const u32 grow = key >> 1, ghalf = key & 1u;
            const u32 nbhi = (u32)(lane >> 4);
#pragma unroll
            for (int nbb = 0; nbb < 4; nbb += 2) {
                u32 nbp = (u32)nbb + nbhi;
                u32 chunk = ((ghalf << 2) + nbp) ^ (grow & 7u);
                u32 ga = Goff + grow * 128 + chunk * 16;
                u32 g00, g01, g10, g11;
                ldsm4t(g00, g01, g10, g11, ga);
                mma_bf16(ofrag[0][nbb],     pa[0], g00, g01);
                mma_bf16(ofrag[1][nbb],     pa[1], g00, g01);
                mma_bf16(ofrag[0][nbb + 1], pa[0], g10, g11);
                mma_bf16(ofrag[1][nbb + 1], pa[1], g10, g11);
            }
        }
        __syncthreads();
        buf ^= 1;
    }

    // ---------------- store unnormalized partials ----------------
    const u32 qq = (u32)(lane & 3);
    float* ybase = g_yp + (size_t)split * (Bsz * HW * C2d);
#pragma unroll
    for (int qb = 0; qb < 2; ++qb) {
        float r0 = rsum[qb][0], r1 = rsum[qb][1];
        r0 += __shfl_xor_sync(0xFFFFFFFF, r0, 1);
        r0 += __shfl_xor_sync(0xFFFFFFFF, r0, 2);
        r1 += __shfl_xor_sync(0xFFFFFFFF, r1, 1);
        r1 += __shfl_xor_sync(0xFFFFFFFF, r1, 2);

        const int row0 = q0 + 32 * wid + 16 * qb + (lane >> 2);
        float* y0 = ybase + ((size_t)(b * HW + row0)) * C2d + 2 * qq;
        float* y1 = y0 + 8 * C2d;
#pragma unroll
        for (int nb = 0; nb < 4; ++nb) {
            *reinterpret_cast<float2*>(y0 + nb * 8) =
                make_float2(ofrag[qb][nb][0], ofrag[qb][nb][1]);
            *reinterpret_cast<float2*>(y1 + nb * 8) =
                make_float2(ofrag[qb][nb][2], ofrag[qb][nb][3]);
        }
        if (qq == 0) {
            g_rs[(size_t)split * (Bsz * HW) + b * HW + row0] = r0;
            g_rs[(size_t)split * (Bsz * HW) + b * HW + row0 + 8] = r1;
        }
    }
}

// ===========================================================================
// Kernel 3: combine partials + out-conv + residual
// ===========================================================================
__global__ void __launch_bounds__(128) combine_out_kernel(
    const float* __restrict__ x, const float* __restrict__ w,
    const float* __restrict__ bias, float* __restrict__ out)
{
    __shared__ float ws[C2d * Cin];   // [c2][o]
    __shared__ float bs[Cin];
    const int tid = threadIdx.x;
    for (int i = tid; i < C2d * Cin; i += 128) { int c2 = i >> 6, o = i & 63; ws[i] = w[o * C2d + c2]; }
    if (tid < Cin) bs[tid] = bias[tid];
    __syncthreads();

    const int p = blockIdx.x * 128 + tid;
    const int b = p >> 14, n = p & (HW - 1);

    const float inv = 1.0f / (g_rs[p] + g_rs[Bsz * HW + p]);
    float yv[C2d];
    {
        const float4* ya = reinterpret_cast<const float4*>(g_yp + (size_t)p * C2d);
        const float4* yb = reinterpret_cast<const float4*>(
            g_yp + (size_t)(Bsz * HW * C2d) + (size_t)p * C2d);
#pragma unroll
        for (int i = 0; i < 8; ++i) {
            float4 a = ya[i], bq = yb[i];
            yv[4*i+0] = (a.x + bq.x) * inv;
            yv[4*i+1] = (a.y + bq.y) * inv;
            yv[4*i+2] = (a.z + bq.z) * inv;
            yv[4*i+3] = (a.w + bq.w) * inv;
        }
    }

    float acc[Cin];
#pragma unroll
    for (int o = 0; o < Cin; ++o) acc[o] = bs[o];
#pragma unroll 4
    for (int c2 = 0; c2 < C2d; ++c2) {
        float yc = yv[c2];
        const float4* wr = reinterpret_cast<const float4*>(ws + c2 * Cin);
#pragma unroll
        for (int k = 0; k < 16; ++k) {
            float4 wv = wr[k];
            acc[4*k+0] = fmaf(yc, wv.x, acc[4*k+0]);
            acc[4*k+1] = fmaf(yc, wv.y, acc[4*k+1]);
            acc[4*k+2] = fmaf(yc, wv.z, acc[4*k+2]);
            acc[4*k+3] = fmaf(yc, wv.w, acc[4*k+3]);
        }
    }
    const float* xb = x + (size_t)b * Cin * HW + n;
    float* ob = out + (size_t)b * Cin * HW + n;
#pragma unroll
    for (int o = 0; o < Cin; ++o)
        ob[(size_t)o * HW] = acc[o] + xb[(size_t)o * HW];
}

// ===========================================================================
extern "C" void kernel_launch(void* const* d_in, const int* in_sizes, int n_in,
                              void* d_out, int out_size)
{
    const float* x       = (const float*)d_in[0];
    const float* w_theta = (const float*)d_in[1];
    const float* b_theta = (const float*)d_in[2];
    const float* w_phi   = (const float*)d_in[3];
    const float* b_phi   = (const float*)d_in[4];
    const float* w_g     = (const float*)d_in[5];
    const float* b_g     = (const float*)d_in[6];
    const float* w_out   = (const float*)d_in[7];
    const float* b_out   = (const float*)d_in[8];
    float* out = (float*)d_out;

    conv_pool_kernel<<<dim3((Bsz * HW4) / 128, 2), 128>>>(x, w_phi, b_phi, w_g, b_g);

    cudaFuncSetAttribute(attn_fused_kernel,
                         cudaFuncAttributeMaxDynamicSharedMemorySize, SMEM_AT);
    attn_fused_kernel<<<dim3(128, Bsz, NSPL), 128, SMEM_AT>>>(x, w_theta, b_theta);

    combine_out_kernel<<<(Bsz * HW) / 128, 128>>>(x, w_out, b_out, out);
}

// round 10
// speedup vs baseline: 5.8861x; 1.0380x over previous
#include <cuda_runtime.h>
#include <cuda_bf16.h>
#include <cstdint>

#define Bsz   4
#define Cin   64
#define C2d   32
#define HW    16384
#define HW4   4096
#define NTI   32      // key tiles of 128
#define NSPL  2       // key splits

typedef unsigned int u32;

// Scratch (device globals)
__device__ __align__(1024) float g_phi [Bsz * HW4 * C2d];      // tf32-rounded, swizzled rows
__device__ __align__(1024) uint4 g_gB4 [Bsz * HW4 * 4];        // bf16, custom-swizzled
__device__ __align__(1024) float g_yp  [NSPL * Bsz * HW * C2d];// unnormalized y partials
__device__ __align__(1024) float g_rs  [NSPL * Bsz * HW];      // partial row sums

// ---------------- helpers ----------------
__device__ __forceinline__ u32 smem_u32(const void* p) { return (u32)__cvta_generic_to_shared(p); }
__device__ __forceinline__ void cp16(u32 dst, const void* src) {
    asm volatile("cp.async.cg.shared.global [%0], [%1], 16;" :: "r"(dst), "l"(src));
}
__device__ __forceinline__ void cp_commit() { asm volatile("cp.async.commit_group;"); }
template <int N> __device__ __forceinline__ void cp_wait() {
    asm volatile("cp.async.wait_group %0;" :: "n"(N));
}
__device__ __forceinline__ void ldsm4(u32& r0, u32& r1, u32& r2, u32& r3, u32 a) {
    asm volatile("ldmatrix.sync.aligned.m8n8.x4.shared.b16 {%0,%1,%2,%3}, [%4];"
                 : "=r"(r0), "=r"(r1), "=r"(r2), "=r"(r3) : "r"(a));
}
__device__ __forceinline__ void ldsm4t(u32& r0, u32& r1, u32& r2, u32& r3, u32 a) {
    asm volatile("ldmatrix.sync.aligned.m8n8.x4.trans.shared.b16 {%0,%1,%2,%3}, [%4];"
                 : "=r"(r0), "=r"(r1), "=r"(r2), "=r"(r3) : "r"(a));
}
__device__ __forceinline__ u32 to_tf32(float f) {
    u32 r; asm("cvt.rna.tf32.f32 %0, %1;" : "=r"(r) : "f"(f)); return r;
}
__device__ __forceinline__ float t32f(float f) { return __uint_as_float(to_tf32(f)); }
__device__ __forceinline__ u32 pbf2(float lo, float hi) {
    u32 r; asm("cvt.rn.bf16x2.f32 %0, %1, %2;" : "=r"(r) : "f"(hi), "f"(lo)); return r;
}
__device__ __forceinline__ float ex2f(float x) {
    float r; asm("ex2.approx.f32 %0, %1;" : "=f"(r) : "f"(x)); return r;
}
__device__ __forceinline__ void sts128(u32 a, u32 c0, u32 c1, u32 c2, u32 c3) {
    asm volatile("st.shared.v4.b32 [%0], {%1,%2,%3,%4};"
                 :: "r"(a), "r"(c0), "r"(c1), "r"(c2), "r"(c3) : "memory");
}
__device__ __forceinline__ void mma_tf32(float* c, const u32* a, u32 b0, u32 b1) {
    asm volatile("mma.sync.aligned.m16n8k8.row.col.f32.tf32.tf32.f32 "
                 "{%0,%1,%2,%3}, {%4,%5,%6,%7}, {%8,%9}, {%0,%1,%2,%3};"
                 : "+f"(c[0]), "+f"(c[1]), "+f"(c[2]), "+f"(c[3])
                 : "r"(a[0]), "r"(a[1]), "r"(a[2]), "r"(a[3]), "r"(b0), "r"(b1));
}
__device__ __forceinline__ void mma_bf16(float* c, const u32* a, u32 b0, u32 b1) {
    asm volatile("mma.sync.aligned.m16n8k16.row.col.f32.bf16.bf16.f32 "
                 "{%0,%1,%2,%3}, {%4,%5,%6,%7}, {%8,%9}, {%0,%1,%2,%3};"
                 : "+f"(c[0]), "+f"(c[1]), "+f"(c[2]), "+f"(c[3])
                 : "r"(a[0]), "r"(a[1]), "r"(a[2]), "r"(a[3]), "r"(b0), "r"(b1));
}

// ===========================================================================
// Kernel 1: phi & g producers. 4 threads per pooled pixel (one per pool pos),
// shuffle-max reduce in lane quads. blockIdx.y = which conv.
// ===========================================================================
__global__ void __launch_bounds__(256) conv_pool_kernel(
    const float* __restrict__ x,
    const float* __restrict__ wphi, const float* __restrict__ bphi,
    const float* __restrict__ wg,   const float* __restrict__ bg)
{
    __shared__ float ws[Cin * C2d];
    __shared__ float bs[C2d];
    const int tid = threadIdx.x;
    const int sel = blockIdx.y;
    const float* wsrc = sel ? wg : wphi;
    const float* bsrc = sel ? bg : bphi;
    for (int i = tid; i < Cin * C2d; i += 256) {
        int c = i >> 5, o = i & 31;
        ws[i] = wsrc[o * Cin + c];
    }
    if (tid < C2d) bs[tid] = bsrc[tid];
    __syncthreads();

    const int idx = blockIdx.x * 256 + tid;    // 0 .. Bsz*HW4*4-1
    const int px = idx & 3;                    // pool position (bit0 = col, bit1 = row)
    const int m  = (idx >> 2) & (HW4 - 1);     // pooled pixel
    const int b  = idx >> 14;
    const int h2 = m >> 6, w2 = m & 63;
    const int n  = (2 * h2 + (px >> 1)) * 128 + 2 * w2 + (px & 1);
    const float* xb = x + (size_t)b * Cin * HW + n;

    float acc[C2d];
#pragma unroll
    for (int o = 0; o < C2d; ++o) acc[o] = bs[o];
    const float4* ws4 = reinterpret_cast<const float4*>(ws);
#pragma unroll 4
    for (int c = 0; c < Cin; ++c) {
        float xv = xb[(size_t)c * HW];
#pragma unroll
        for (int k = 0; k < 8; ++k) {
            float4 wv = ws4[c * 8 + k];
            acc[4*k+0] = fmaf(xv, wv.x, acc[4*k+0]);
            acc[4*k+1] = fmaf(xv, wv.y, acc[4*k+1]);
            acc[4*k+2] = fmaf(xv, wv.z, acc[4*k+2]);
            acc[4*k+3] = fmaf(xv, wv.w, acc[4*k+3]);
        }
    }
    // max-reduce over the 4 pool positions (lane quads)
#pragma unroll
    for (int o = 0; o < C2d; ++o)
        acc[o] = fmaxf(acc[o], __shfl_xor_sync(0xFFFFFFFF, acc[o], 1));
#pragma unroll
    for (int o = 0; o < C2d; ++o)
        acc[o] = fmaxf(acc[o], __shfl_xor_sync(0xFFFFFFFF, acc[o], 2));

    if (px == 0) {
        const int pidx = b * HW4 + m;
        if (sel == 0) {
            const int sw = pidx & 7;
            float4* d4 = reinterpret_cast<float4*>(g_phi + (size_t)pidx * C2d);
#pragma unroll
            for (int j = 0; j < 8; ++j)
                d4[j ^ sw] = make_float4(t32f(acc[4*j]), t32f(acc[4*j+1]),
                                         t32f(acc[4*j+2]), t32f(acc[4*j+3]));
        } else {
            uint4* base = g_gB4 + ((size_t)b * HW4 + (size_t)(m & ~127)) * 4;
            const int ml = m & 127, row = ml >> 1, half = ml & 1;
#pragma unroll
            for (int c = 0; c < 4; ++c) {
                uint4 v;
                v.x = pbf2(acc[8*c+0], acc[8*c+1]);
                v.y = pbf2(acc[8*c+2], acc[8*c+3]);
                v.z = pbf2(acc[8*c+4], acc[8*c+5]);
                v.w = pbf2(acc[8*c+6], acc[8*c+7]);
                int chunk = (half * 4 + c) ^ (row & 7);
                base[row * 8 + chunk] = v;
            }
        }
    }
}

// ===========================================================================
// Kernel 2: fused theta-conv + flash attention, 2-way key split.
// grid=(128,4,2), 128 thr (4 warps x m32). Writes unnormalized partials.
// SMEM: Q 16K @0 | KV 2x24K @16384 = 64 KB; 3 CTAs/SM.
// ===========================================================================
#define OFF_Q    0
#define OFF_KV   16384
#define KVSTRIDE 24576
#define SMEM_AT  (16384 + 2 * 24576)

__global__ void __launch_bounds__(128, 3) attn_fused_kernel(
    const float* __restrict__ x,
    const float* __restrict__ w_theta, const float* __restrict__ b_theta)
{
    extern __shared__ __align__(1024) char smem[];
    float* smf = reinterpret_cast<float*>(smem);
    const u32 sb = smem_u32(smem);
    const int tid = threadIdx.x, wid = tid >> 5, lane = tid & 31;
    const int b = blockIdx.y, q0 = blockIdx.x * 128;
    const int split = blockIdx.z;
    const int t0 = split * (NTI / NSPL), t1 = t0 + NTI / NSPL;
    const float LOG2E = 1.44269504088896340736f;

    // ---------------- Prologue: theta into Q smem ----------------
    {
        const float* xs = x + (size_t)b * Cin * HW + q0;
#pragma unroll
        for (int i = 0; i < 16; ++i) {
            int idx = tid + 128 * i;
            int c = idx >> 5, off = idx & 31;
            cp16(sb + OFF_KV + (u32)idx * 16, xs + (size_t)c * HW + off * 4);
        }
        cp_commit();
#pragma unroll
        for (int i = 0; i < 16; ++i) {
            int idx = tid + 128 * i;
            int c = idx >> 5, o = idx & 31;
            smf[(OFF_KV + 32768) / 4 + idx] = w_theta[o * Cin + c];
        }
        cp_wait<0>();
        __syncthreads();

        const int p = tid;
        float acc[C2d];
#pragma unroll
        for (int j = 0; j < C2d; ++j) acc[j] = __ldg(b_theta + j);
        const float* xs_s = smf + OFF_KV / 4;
        const float* ws_s = smf + (OFF_KV + 32768) / 4;
#pragma unroll 4
        for (int c = 0; c < Cin; ++c) {
            float xv = xs_s[c * 128 + p];
            const float4* wr = reinterpret_cast<const float4*>(ws_s + c * 32);
#pragma unroll
            for (int k = 0; k < 8; ++k) {
                float4 wv = wr[k];
                acc[4*k+0] = fmaf(xv, wv.x, acc[4*k+0]);
                acc[4*k+1] = fmaf(xv, wv.y, acc[4*k+1]);
                acc[4*k+2] = fmaf(xv, wv.z, acc[4*k+2]);
                acc[4*k+3] = fmaf(xv, wv.w, acc[4*k+3]);
            }
        }
#pragma unroll
        for (int ch = 0; ch < 8; ++ch) {
            u32 a = sb + OFF_Q + (u32)p * 128 + (u32)((ch ^ (p & 7)) * 16);
            sts128(a, to_tf32(acc[4*ch+0] * LOG2E), to_tf32(acc[4*ch+1] * LOG2E),
                      to_tf32(acc[4*ch+2] * LOG2E), to_tf32(acc[4*ch+3] * LOG2E));
        }
        __syncthreads();
    }

    // ---------------- KV pipeline ----------------
    auto load_kv = [&](int t, int bufi) {
        u32 d = sb + OFF_KV + (u32)bufi * KVSTRIDE;
        const char* sp = (const char*)(g_phi + (size_t)(b * HW4 + t * 128) * C2d);
#pragma unroll
        for (int i = 0; i < 8; ++i) {
            int idx = tid + 128 * i;
            cp16(d + (u32)idx * 16, sp + (size_t)idx * 16);
        }
        const char* sg = (const char*)(g_gB4 + ((size_t)b * HW4 + (size_t)t * 128) * 4);
#pragma unroll
        for (int i = 0; i < 4; ++i) {
            int idx = tid + 128 * i;
            cp16(d + 16384 + (u32)idx * 16, sg + (size_t)idx * 16);
        }
    };
    load_kv(t0, 0);
    cp_commit();
    cp_wait<0>();
    __syncthreads();

    // Q A-frags: 2 q-subblocks of m16 per warp
    u32 qh[2][4][4];
#pragma unroll
    for (int qb = 0; qb < 2; ++qb)
#pragma unroll
    for (int ks = 0; ks < 4; ++ks) {
        u32 row = (u32)(32 * wid + 16 * qb + ((lane >> 3) & 1) * 8 + (lane & 7));
        u32 chunk = (u32)(2 * ks + (lane >> 4));
        u32 a = sb + OFF_Q + row * 128 + ((chunk ^ (lane & 7u))) * 16;
        ldsm4(qh[qb][ks][0], qh[qb][ks][1], qh[qb][ks][2], qh[qb][ks][3], a);
    }

    float ofrag[2][4][4];
#pragma unroll
    for (int qb = 0; qb < 2; ++qb)
#pragma unroll
    for (int nb = 0; nb < 4; ++nb)
#pragma unroll
        for (int i = 0; i < 4; ++i) ofrag[qb][nb][i] = 0.f;
    float rsum[2][2] = {{0.f, 0.f}, {0.f, 0.f}};

    int buf = 0;
    for (int t = t0; t < t1; ++t) {
        if (t + 1 < t1) { load_kv(t + 1, buf ^ 1); cp_commit(); cp_wait<1>(); }
        else            { cp_wait<0>(); }
        __syncthreads();

        const u32 Koff = sb + OFF_KV + (u32)buf * KVSTRIDE;
        const u32 Goff = Koff + 16384;

#pragma unroll
        for (int jp = 0; jp < 8; ++jp) {
            const u32 kb = (u32)(jp * 16);
            float s[2][2][4];
#pragma unroll
            for (int qb = 0; qb < 2; ++qb)
#pragma unroll
                for (int blk = 0; blk < 2; ++blk)
#pragma unroll
                    for (int i = 0; i < 4; ++i) s[qb][blk][i] = 0.f;

            const u32 krow = kb + (u32)(((lane >> 4) << 3) + (lane & 7));
#pragma unroll
            for (int ks = 0; ks < 4; ++ks) {
                u32 ch = (u32)(2 * ks) + ((u32)(lane >> 3) & 1u);
                u32 a = Koff + krow * 128 + ((ch ^ (lane & 7u))) * 16;
                u32 x0, x1, y0, y1;
                ldsm4(x0, x1, y0, y1, a);
                mma_tf32(s[0][0], qh[0][ks], x0, x1);
                mma_tf32(s[1][0], qh[1][ks], x0, x1);
                mma_tf32(s[0][1], qh[0][ks], y0, y1);
                mma_tf32(s[1][1], qh[1][ks], y0, y1);
            }

            u32 pa[2][4];
#pragma unroll
            for (int qb = 0; qb < 2; ++qb) {
                float e00 = ex2f(s[qb][0][0]), e01 = ex2f(s[qb][0][1]);
                float e02 = ex2f(s[qb][0][2]), e03 = ex2f(s[qb][0][3]);
                float e10 = ex2f(s[qb][1][0]), e11 = ex2f(s[qb][1][1]);
                float e12 = ex2f(s[qb][1][2]), e13 = ex2f(s[qb][1][3]);
                rsum[qb][0] += (e00 + e01) + (e10 + e11);
                rsum[qb][1] += (e02 + e03) + (e12 + e13);
                pa[qb][0] = pbf2(e00, e01);
                pa[qb][1] = pbf2(e02, e03);
                pa[qb][2] = pbf2(e10, e11);
                pa[qb][3] = pbf2(e12, e13);
            }

            const u32 key = kb + (u32)(lane & 15);
            const u32 grow = key >> 1, ghalf = key & 1u;
            const u32 nbhi = (u32)(lane >> 4);
#pragma unroll
            for (int nbb = 0; nbb < 4; nbb += 2) {
                u32 nbp = (u32)nbb + nbhi;
                u32 chunk = ((ghalf << 2) + nbp) ^ (grow & 7u);
                u32 ga = Goff + grow * 128 + chunk * 16;
                u32 g00, g01, g10, g11;
                ldsm4t(g00, g01, g10, g11, ga);
                mma_bf16(ofrag[0][nbb],     pa[0], g00, g01);
                mma_bf16(ofrag[1][nbb],     pa[1], g00, g01);
                mma_bf16(ofrag[0][nbb + 1], pa[0], g10, g11);
                mma_bf16(ofrag[1][nbb + 1], pa[1], g10, g11);
            }
        }
        __syncthreads();
        buf ^= 1;
    }

    // ---------------- store unnormalized partials ----------------
    const u32 qq = (u32)(lane & 3);
    float* ybase = g_yp + (size_t)split * (Bsz * HW * C2d);
#pragma unroll
    for (int qb = 0; qb < 2; ++qb) {
        float r0 = rsum[qb][0], r1 = rsum[qb][1];
        r0 += __shfl_xor_sync(0xFFFFFFFF, r0, 1);
        r0 += __shfl_xor_sync(0xFFFFFFFF, r0, 2);
        r1 += __shfl_xor_sync(0xFFFFFFFF, r1, 1);
        r1 += __shfl_xor_sync(0xFFFFFFFF, r1, 2);

        const int row0 = q0 + 32 * wid + 16 * qb + (lane >> 2);
        float* y0 = ybase + ((size_t)(b * HW + row0)) * C2d + 2 * qq;
        float* y1 = y0 + 8 * C2d;
#pragma unroll
        for (int nb = 0; nb < 4; ++nb) {
            *reinterpret_cast<float2*>(y0 + nb * 8) =
                make_float2(ofrag[qb][nb][0], ofrag[qb][nb][1]);
            *reinterpret_cast<float2*>(y1 + nb * 8) =
                make_float2(ofrag[qb][nb][2], ofrag[qb][nb][3]);
        }
        if (qq == 0) {
            g_rs[(size_t)split * (Bsz * HW) + b * HW + row0] = r0;
            g_rs[(size_t)split * (Bsz * HW) + b * HW + row0 + 8] = r1;
        }
    }
}

// ===========================================================================
// Kernel 3: combine partials + out-conv + residual. 2 threads per pixel.
// ===========================================================================
__global__ void __launch_bounds__(256) combine_out_kernel(
    const float* __restrict__ x, const float* __restrict__ w,
    const float* __restrict__ bias, float* __restrict__ out)
{
    __shared__ float ws[C2d * Cin];   // [c2][o]
    __shared__ float bs[Cin];
    const int tid = threadIdx.x;
    for (int i = tid; i < C2d * Cin; i += 256) { int c2 = i >> 6, o = i & 63; ws[i] = w[o * C2d + c2]; }
    if (tid < Cin) bs[tid] = bias[tid];
    __syncthreads();

    const int p = blockIdx.x * 128 + (tid & 127);
    const int h = tid >> 7;                      // output-channel half
    const int b = p >> 14, n = p & (HW - 1);

    const float inv = 1.0f / (g_rs[p] + g_rs[Bsz * HW + p]);
    float yv[C2d];
    {
        const float4* ya = reinterpret_cast<const float4*>(g_yp + (size_t)p * C2d);
        const float4* yb = reinterpret_cast<const float4*>(
            g_yp + (size_t)(Bsz * HW * C2d) + (size_t)p * C2d);
#pragma unroll
        for (int i = 0; i < 8; ++i) {
            float4 a = ya[i], bq = yb[i];
            yv[4*i+0] = (a.x + bq.x) * inv;
            yv[4*i+1] = (a.y + bq.y) * inv;
            yv[4*i+2] = (a.z + bq.z) * inv;
            yv[4*i+3] = (a.w + bq.w) * inv;
        }
    }

    float acc[32];
#pragma unroll
    for (int j = 0; j < 32; ++j) acc[j] = bs[h * 32 + j];
#pragma unroll 4
    for (int c2 = 0; c2 < C2d; ++c2) {
        float yc = yv[c2];
        const float4* wr = reinterpret_cast<const float4*>(ws + c2 * Cin + h * 32);
#pragma unroll
        for (int k = 0; k < 8; ++k) {
            float4 wv = wr[k];
            acc[4*k+0] = fmaf(yc, wv.x, acc[4*k+0]);
            acc[4*k+1] = fmaf(yc, wv.y, acc[4*k+1]);
            acc[4*k+2] = fmaf(yc, wv.z, acc[4*k+2]);
            acc[4*k+3] = fmaf(yc, wv.w, acc[4*k+3]);
        }
    }
    const float* xb = x + (size_t)b * Cin * HW + n;
    float* ob = out + (size_t)b * Cin * HW + n;
#pragma unroll
    for (int j = 0; j < 32; ++j) {
        int o = h * 32 + j;
        ob[(size_t)o * HW] = acc[j] + xb[(size_t)o * HW];
    }
}

// ===========================================================================
extern "C" void kernel_launch(void* const* d_in, const int* in_sizes, int n_in,
                              void* d_out, int out_size)
{
    const float* x       = (const float*)d_in[0];
    const float* w_theta = (const float*)d_in[1];
    const float* b_theta = (const float*)d_in[2];
    const float* w_phi   = (const float*)d_in[3];
    const float* b_phi   = (const float*)d_in[4];
    const float* w_g     = (const float*)d_in[5];
    const float* b_g     = (const float*)d_in[6];
    const float* w_out   = (const float*)d_in[7];
    const float* b_out   = (const float*)d_in[8];
    float* out = (float*)d_out;

    conv_pool_kernel<<<dim3((Bsz * HW4 * 4) / 256, 2), 256>>>(x, w_phi, b_phi, w_g, b_g);

    cudaFuncSetAttribute(attn_fused_kernel,
                         cudaFuncAttributeMaxDynamicSharedMemorySize, SMEM_AT);
    attn_fused_kernel<<<dim3(128, Bsz, NSPL), 128, SMEM_AT>>>(x, w_theta, b_theta);

    combine_out_kernel<<<(Bsz * HW) / 128, 256>>>(x, w_out, b_out, out);
}

// round 11
// speedup vs baseline: 7.0870x; 1.2040x over previous
#include <cuda_runtime.h>
#include <cuda_bf16.h>
#include <cstdint>

#define Bsz   4
#define Cin   64
#define C2d   32
#define HW    16384
#define HW4   4096
#define NTI   32      // key tiles of 128
#define NSPL  2       // key splits

typedef unsigned int u32;

// Scratch (device globals)
__device__ __align__(1024) uint4 g_phH4[Bsz * HW4 * 4];        // fp16 phi, packed 64B/key, G-style swizzle
__device__ __align__(1024) uint4 g_gB4 [Bsz * HW4 * 4];        // bf16 g, packed 64B/key
__device__ __align__(1024) float g_yp  [NSPL * Bsz * HW * C2d];// unnormalized y partials
__device__ __align__(1024) float g_rs  [NSPL * Bsz * HW];      // partial row sums

// ---------------- helpers ----------------
__device__ __forceinline__ u32 smem_u32(const void* p) { return (u32)__cvta_generic_to_shared(p); }
__device__ __forceinline__ void cp16(u32 dst, const void* src) {
    asm volatile("cp.async.cg.shared.global [%0], [%1], 16;" :: "r"(dst), "l"(src));
}
__device__ __forceinline__ void cp_commit() { asm volatile("cp.async.commit_group;"); }
template <int N> __device__ __forceinline__ void cp_wait() {
    asm volatile("cp.async.wait_group %0;" :: "n"(N));
}
__device__ __forceinline__ void ldsm4(u32& r0, u32& r1, u32& r2, u32& r3, u32 a) {
    asm volatile("ldmatrix.sync.aligned.m8n8.x4.shared.b16 {%0,%1,%2,%3}, [%4];"
                 : "=r"(r0), "=r"(r1), "=r"(r2), "=r"(r3) : "r"(a));
}
__device__ __forceinline__ void ldsm4t(u32& r0, u32& r1, u32& r2, u32& r3, u32 a) {
    asm volatile("ldmatrix.sync.aligned.m8n8.x4.trans.shared.b16 {%0,%1,%2,%3}, [%4];"
                 : "=r"(r0), "=r"(r1), "=r"(r2), "=r"(r3) : "r"(a));
}
__device__ __forceinline__ u32 pbf2(float lo, float hi) {
    u32 r; asm("cvt.rn.bf16x2.f32 %0, %1, %2;" : "=r"(r) : "f"(hi), "f"(lo)); return r;
}
__device__ __forceinline__ u32 pf16(float lo, float hi) {
    u32 r; asm("cvt.rn.f16x2.f32 %0, %1, %2;" : "=r"(r) : "f"(hi), "f"(lo)); return r;
}
__device__ __forceinline__ float ex2f(float x) {
    float r; asm("ex2.approx.f32 %0, %1;" : "=f"(r) : "f"(x)); return r;
}
__device__ __forceinline__ void sts128(u32 a, u32 c0, u32 c1, u32 c2, u32 c3) {
    asm volatile("st.shared.v4.b32 [%0], {%1,%2,%3,%4};"
                 :: "r"(a), "r"(c0), "r"(c1), "r"(c2), "r"(c3) : "memory");
}
__device__ __forceinline__ void mma_f16(float* c, const u32* a, u32 b0, u32 b1) {
    asm volatile("mma.sync.aligned.m16n8k16.row.col.f32.f16.f16.f32 "
                 "{%0,%1,%2,%3}, {%4,%5,%6,%7}, {%8,%9}, {%0,%1,%2,%3};"
                 : "+f"(c[0]), "+f"(c[1]), "+f"(c[2]), "+f"(c[3])
                 : "r"(a[0]), "r"(a[1]), "r"(a[2]), "r"(a[3]), "r"(b0), "r"(b1));
}
__device__ __forceinline__ void mma_bf16(float* c, const u32* a, u32 b0, u32 b1) {
    asm volatile("mma.sync.aligned.m16n8k16.row.col.f32.bf16.bf16.f32 "
                 "{%0,%1,%2,%3}, {%4,%5,%6,%7}, {%8,%9}, {%0,%1,%2,%3};"
                 : "+f"(c[0]), "+f"(c[1]), "+f"(c[2]), "+f"(c[3])
                 : "r"(a[0]), "r"(a[1]), "r"(a[2]), "r"(a[3]), "r"(b0), "r"(b1));
}

// ===========================================================================
// Kernel 1: phi (fp16 packed) & g (bf16 packed) producers. 4 threads per
// pooled pixel, shuffle-max reduce. blockIdx.y = which conv.
// ===========================================================================
__global__ void __launch_bounds__(256) conv_pool_kernel(
    const float* __restrict__ x,
    const float* __restrict__ wphi, const float* __restrict__ bphi,
    const float* __restrict__ wg,   const float* __restrict__ bg)
{
    __shared__ float ws[Cin * C2d];
    __shared__ float bs[C2d];
    const int tid = threadIdx.x;
    const int sel = blockIdx.y;
    const float* wsrc = sel ? wg : wphi;
    const float* bsrc = sel ? bg : bphi;
    for (int i = tid; i < Cin * C2d; i += 256) {
        int c = i >> 5, o = i & 31;
        ws[i] = wsrc[o * Cin + c];
    }
    if (tid < C2d) bs[tid] = bsrc[tid];
    __syncthreads();

    const int idx = blockIdx.x * 256 + tid;    // 0 .. Bsz*HW4*4-1
    const int px = idx & 3;                    // pool position
    const int m  = (idx >> 2) & (HW4 - 1);     // pooled pixel
    const int b  = idx >> 14;
    const int h2 = m >> 6, w2 = m & 63;
    const int n  = (2 * h2 + (px >> 1)) * 128 + 2 * w2 + (px & 1);
    const float* xb = x + (size_t)b * Cin * HW + n;

    float acc[C2d];
#pragma unroll
    for (int o = 0; o < C2d; ++o) acc[o] = bs[o];
    const float4* ws4 = reinterpret_cast<const float4*>(ws);
#pragma unroll 4
    for (int c = 0; c < Cin; ++c) {
        float xv = xb[(size_t)c * HW];
#pragma unroll
        for (int k = 0; k < 8; ++k) {
            float4 wv = ws4[c * 8 + k];
            acc[4*k+0] = fmaf(xv, wv.x, acc[4*k+0]);
            acc[4*k+1] = fmaf(xv, wv.y, acc[4*k+1]);
            acc[4*k+2] = fmaf(xv, wv.z, acc[4*k+2]);
            acc[4*k+3] = fmaf(xv, wv.w, acc[4*k+3]);
        }
    }
#pragma unroll
    for (int o = 0; o < C2d; ++o)
        acc[o] = fmaxf(acc[o], __shfl_xor_sync(0xFFFFFFFF, acc[o], 1));
#pragma unroll
    for (int o = 0; o < C2d; ++o)
        acc[o] = fmaxf(acc[o], __shfl_xor_sync(0xFFFFFFFF, acc[o], 2));

    if (px == 0) {
        // packed layout (both phi & g): 64B per key, phys row = key>>1 (128B),
        // half = key&1, chunk = (half*4 + c) ^ (row & 7)
        uint4* base = (sel ? g_gB4 : g_phH4) + ((size_t)b * HW4 + (size_t)(m & ~127)) * 4;
        const int ml = m & 127, row = ml >> 1, half = ml & 1;
#pragma unroll
        for (int c = 0; c < 4; ++c) {
            uint4 v;
            if (sel) {
                v.x = pbf2(acc[8*c+0], acc[8*c+1]);
                v.y = pbf2(acc[8*c+2], acc[8*c+3]);
                v.z = pbf2(acc[8*c+4], acc[8*c+5]);
                v.w = pbf2(acc[8*c+6], acc[8*c+7]);
            } else {
                v.x = pf16(acc[8*c+0], acc[8*c+1]);
                v.y = pf16(acc[8*c+2], acc[8*c+3]);
                v.z = pf16(acc[8*c+4], acc[8*c+5]);
                v.w = pf16(acc[8*c+6], acc[8*c+7]);
            }
            int chunk = (half * 4 + c) ^ (row & 7);
            base[row * 8 + chunk] = v;
        }
    }
}

// ===========================================================================
// Kernel 2: fused theta-conv + flash attention (fp16 QK, bf16 PV), 2-way
// key split. grid=(128,4,2), 128 thr (4 warps x m32).
// SMEM: Q 8K @0 | KV 2x16K @8192 (40K steady; 48K transient in prologue)
// ===========================================================================
#define OFF_Q    0
#define OFF_KV   8192
#define KVSTRIDE 16384
#define SMEM_AT  (8192 + 32768 + 8192)   // prologue: Q | x (32K) | w_theta (8K)

__global__ void __launch_bounds__(128, 3) attn_fused_kernel(
    const float* __restrict__ x,
    const float* __restrict__ w_theta, const float* __restrict__ b_theta)
{
    extern __shared__ __align__(1024) char smem[];
    float* smf = reinterpret_cast<float*>(smem);
    const u32 sb = smem_u32(smem);
    const int tid = threadIdx.x, wid = tid >> 5, lane = tid & 31;
    const int b = blockIdx.y, q0 = blockIdx.x * 128;
    const int split = blockIdx.z;
    const int t0 = split * (NTI / NSPL), t1 = t0 + NTI / NSPL;
    const float LOG2E = 1.44269504088896340736f;

    // ---------------- Prologue: theta (x LOG2E, fp16) into Q smem ----------
    {
        const float* xs = x + (size_t)b * Cin * HW + q0;
#pragma unroll
        for (int i = 0; i < 16; ++i) {
            int idx = tid + 128 * i;
            int c = idx >> 5, off = idx & 31;
            cp16(sb + OFF_KV + (u32)idx * 16, xs + (size_t)c * HW + off * 4);
        }
        cp_commit();
#pragma unroll
        for (int i = 0; i < 16; ++i) {
            int idx = tid + 128 * i;
            int c = idx >> 5, o = idx & 31;
            smf[(OFF_KV + 32768) / 4 + idx] = w_theta[o * Cin + c];
        }
        cp_wait<0>();
        __syncthreads();

        const int p = tid;
        float acc[C2d];
#pragma unroll
        for (int j = 0; j < C2d; ++j) acc[j] = __ldg(b_theta + j);
        const float* xs_s = smf + OFF_KV / 4;
        const float* ws_s = smf + (OFF_KV + 32768) / 4;
#pragma unroll 4
        for (int c = 0; c < Cin; ++c) {
            float xv = xs_s[c * 128 + p];
            const float4* wr = reinterpret_cast<const float4*>(ws_s + c * 32);
#pragma unroll
            for (int k = 0; k < 8; ++k) {
                float4 wv = wr[k];
                acc[4*k+0] = fmaf(xv, wv.x, acc[4*k+0]);
                acc[4*k+1] = fmaf(xv, wv.y, acc[4*k+1]);
                acc[4*k+2] = fmaf(xv, wv.z, acc[4*k+2]);
                acc[4*k+3] = fmaf(xv, wv.w, acc[4*k+3]);
            }
        }
        // pack to fp16 (scaled), write G-style: phys row = p>>1, half = p&1
        const u32 prow = (u32)(p >> 1), phalf = (u32)(p & 1);
#pragma unroll
        for (int c = 0; c < 4; ++c) {
            u32 chunk = ((phalf * 4 + (u32)c) ^ (prow & 7u));
            u32 a = sb + OFF_Q + prow * 128 + chunk * 16;
            sts128(a, pf16(acc[8*c+0] * LOG2E, acc[8*c+1] * LOG2E),
                      pf16(acc[8*c+2] * LOG2E, acc[8*c+3] * LOG2E),
                      pf16(acc[8*c+4] * LOG2E, acc[8*c+5] * LOG2E),
                      pf16(acc[8*c+6] * LOG2E, acc[8*c+7] * LOG2E));
        }
        __syncthreads();
    }

    // ---------------- KV pipeline ----------------
    auto load_kv = [&](int t, int bufi) {
        u32 d = sb + OFF_KV + (u32)bufi * KVSTRIDE;
        const char* sp = (const char*)(g_phH4 + ((size_t)b * HW4 + (size_t)t * 128) * 4);
#pragma unroll
        for (int i = 0; i < 4; ++i) {
            int idx = tid + 128 * i;
            cp16(d + (u32)idx * 16, sp + (size_t)idx * 16);
        }
        const char* sg = (const char*)(g_gB4 + ((size_t)b * HW4 + (size_t)t * 128) * 4);
#pragma unroll
        for (int i = 0; i < 4; ++i) {
            int idx = tid + 128 * i;
            cp16(d + 8192 + (u32)idx * 16, sg + (size_t)idx * 16);
        }
    };
    load_kv(t0, 0);
    cp_commit();
    cp_wait<0>();
    __syncthreads();

    // Q A-frags (fp16 m16k16): 2 q-subblocks x 2 k-steps, 4 regs each
    u32 qf[2][2][4];
#pragma unroll
    for (int qb = 0; qb < 2; ++qb)
#pragma unroll
    for (int ks = 0; ks < 2; ++ks) {
        // mats: (r0-7,kc0),(r8-15,kc0),(r0-7,kc1),(r8-15,kc1) with kc = 2ks+(L>>4)
        u32 r = (u32)(32 * wid + 16 * qb + ((lane >> 3) & 1) * 8 + (lane & 7));
        u32 kc = (u32)(2 * ks) + (u32)(lane >> 4);
        u32 prow = r >> 1, phalf = r & 1u;
        u32 chunk = ((phalf * 4 + kc) ^ (prow & 7u));
        u32 a = sb + OFF_Q + prow * 128 + chunk * 16;
        ldsm4(qf[qb][ks][0], qf[qb][ks][1], qf[qb][ks][2], qf[qb][ks][3], a);
    }

    float ofrag[2][4][4];
#pragma unroll
    for (int qb = 0; qb < 2; ++qb)
#pragma unroll
    for (int nb = 0; nb < 4; ++nb)
#pragma unroll
        for (int i = 0; i < 4; ++i) ofrag[qb][nb][i] = 0.f;
    float rsum[2][2] = {{0.f, 0.f}, {0.f, 0.f}};

    int buf = 0;
    for (int t = t0; t < t1; ++t) {
        if (t + 1 < t1) { load_kv(t + 1, buf ^ 1); cp_commit(); cp_wait<1>(); }
        else            { cp_wait<0>(); }
        __syncthreads();

        const u32 Koff = sb + OFF_KV + (u32)buf * KVSTRIDE;
        const u32 Goff = Koff + 8192;

#pragma unroll
        for (int jp = 0; jp < 8; ++jp) {
            const u32 kb = (u32)(jp * 16);
            float s[2][2][4];
#pragma unroll
            for (int qb = 0; qb < 2; ++qb)
#pragma unroll
                for (int blk = 0; blk < 2; ++blk)
#pragma unroll
                    for (int i = 0; i < 4; ++i) s[qb][blk][i] = 0.f;

            // K B-frags: mats = (blk0,kcs0),(blk0,kcs1),(blk1,kcs0),(blk1,kcs1)
            {
                const u32 blk = (u32)(lane >> 4);
                const u32 kcs = (u32)((lane >> 3) & 1);
                const u32 n = kb + blk * 8 + (u32)(lane & 7);
                const u32 nrow = n >> 1, nhalf = n & 1u;
#pragma unroll
                for (int ks = 0; ks < 2; ++ks) {
                    u32 kc = (u32)(2 * ks) + kcs;
                    u32 chunk = ((nhalf * 4 + kc) ^ (nrow & 7u));
                    u32 a = Koff + nrow * 128 + chunk * 16;
                    u32 b0, b1, b2, b3;
                    ldsm4(b0, b1, b2, b3, a);
                    mma_f16(s[0][0], qf[0][ks], b0, b1);
                    mma_f16(s[1][0], qf[1][ks], b0, b1);
                    mma_f16(s[0][1], qf[0][ks], b2, b3);
                    mma_f16(s[1][1], qf[1][ks], b2, b3);
                }
            }

            u32 pa[2][4];
#pragma unroll
            for (int qb = 0; qb < 2; ++qb) {
                float e00 = ex2f(s[qb][0][0]), e01 = ex2f(s[qb][0][1]);
                float e02 = ex2f(s[qb][0][2]), e03 = ex2f(s[qb][0][3]);
                float e10 = ex2f(s[qb][1][0]), e11 = ex2f(s[qb][1][1]);
                float e12 = ex2f(s[qb][1][2]), e13 = ex2f(s[qb][1][3]);
                rsum[qb][0] += (e00 + e01) + (e10 + e11);
                rsum[qb][1] += (e02 + e03) + (e12 + e13);
                pa[qb][0] = pbf2(e00, e01);
                pa[qb][1] = pbf2(e02, e03);
                pa[qb][2] = pbf2(e10, e11);
                pa[qb][3] = pbf2(e12, e13);
            }

            const u32 key = kb + (u32)(lane & 15);
            const u32 grow = key >> 1, ghalf = key & 1u;
            const u32 nbhi = (u32)(lane >> 4);
#pragma unroll
            for (int nbb = 0; nbb < 4; nbb += 2) {
                u32 nbp = (u32)nbb + nbhi;
                u32 chunk = ((ghalf << 2) + nbp) ^ (grow & 7u);
                u32 ga = Goff + grow * 128 + chunk * 16;
                u32 g00, g01, g10, g11;
                ldsm4t(g00, g01, g10, g11, ga);
                mma_bf16(ofrag[0][nbb],     pa[0], g00, g01);
                mma_bf16(ofrag[1][nbb],     pa[1], g00, g01);
                mma_bf16(ofrag[0][nbb + 1], pa[0], g10, g11);
                mma_bf16(ofrag[1][nbb + 1], pa[1], g10, g11);
            }
        }
        __syncthreads();
        buf ^= 1;
    }

    // ---------------- store unnormalized partials ----------------
    const u32 qq = (u32)(lane & 3);
    float* ybase = g_yp + (size_t)split * (Bsz * HW * C2d);
#pragma unroll
    for (int qb = 0; qb < 2; ++qb) {
        float r0 = rsum[qb][0], r1 = rsum[qb][1];
        r0 += __shfl_xor_sync(0xFFFFFFFF, r0, 1);
        r0 += __shfl_xor_sync(0xFFFFFFFF, r0, 2);
        r1 += __shfl_xor_sync(0xFFFFFFFF, r1, 1);
        r1 += __shfl_xor_sync(0xFFFFFFFF, r1, 2);

        const int row0 = q0 + 32 * wid + 16 * qb + (lane >> 2);
        float* y0 = ybase + ((size_t)(b * HW + row0)) * C2d + 2 * qq;
        float* y1 = y0 + 8 * C2d;
#pragma unroll
        for (int nb = 0; nb < 4; ++nb) {
            *reinterpret_cast<float2*>(y0 + nb * 8) =
                make_float2(ofrag[qb][nb][0], ofrag[qb][nb][1]);
            *reinterpret_cast<float2*>(y1 + nb * 8) =
                make_float2(ofrag[qb][nb][2], ofrag[qb][nb][3]);
        }
        if (qq == 0) {
            g_rs[(size_t)split * (Bsz * HW) + b * HW + row0] = r0;
            g_rs[(size_t)split * (Bsz * HW) + b * HW + row0 + 8] = r1;
        }
    }
}

// ===========================================================================
// Kernel 3: combine partials + out-conv + residual. 2 threads per pixel.
// ===========================================================================
__global__ void __launch_bounds__(256) combine_out_kernel(
    const float* __restrict__ x, const float* __restrict__ w,
    const float* __restrict__ bias, float* __restrict__ out)
{
    __shared__ float ws[C2d * Cin];   // [c2][o]
    __shared__ float bs[Cin];
    const int tid = threadIdx.x;
    for (int i = tid; i < C2d * Cin; i += 256) { int c2 = i >> 6, o = i & 63; ws[i] = w[o * C2d + c2]; }
    if (tid < Cin) bs[tid] = bias[tid];
    __syncthreads();

    const int p = blockIdx.x * 128 + (tid & 127);
    const int h = tid >> 7;                      // output-channel half
    const int b = p >> 14, n = p & (HW - 1);

    const float inv = 1.0f / (g_rs[p] + g_rs[Bsz * HW + p]);
    float yv[C2d];
    {
        const float4* ya = reinterpret_cast<const float4*>(g_yp + (size_t)p * C2d);
        const float4* yb = reinterpret_cast<const float4*>(
            g_yp + (size_t)(Bsz * HW * C2d) + (size_t)p * C2d);
#pragma unroll
        for (int i = 0; i < 8; ++i) {
            float4 a = ya[i], bq = yb[i];
            yv[4*i+0] = (a.x + bq.x) * inv;
            yv[4*i+1] = (a.y + bq.y) * inv;
            yv[4*i+2] = (a.z + bq.z) * inv;
            yv[4*i+3] = (a.w + bq.w) * inv;
        }
    }

    float acc[32];
#pragma unroll
    for (int j = 0; j < 32; ++j) acc[j] = bs[h * 32 + j];
#pragma unroll 4
    for (int c2 = 0; c2 < C2d; ++c2) {
        float yc = yv[c2];
        const float4* wr = reinterpret_cast<const float4*>(ws + c2 * Cin + h * 32);
#pragma unroll
        for (int k = 0; k < 8; ++k) {
            float4 wv = wr[k];
            acc[4*k+0] = fmaf(yc, wv.x, acc[4*k+0]);
            acc[4*k+1] = fmaf(yc, wv.y, acc[4*k+1]);
            acc[4*k+2] = fmaf(yc, wv.z, acc[4*k+2]);
            acc[4*k+3] = fmaf(yc, wv.w, acc[4*k+3]);
        }
    }
    const float* xb = x + (size_t)b * Cin * HW + n;
    float* ob = out + (size_t)b * Cin * HW + n;
#pragma unroll
    for (int j = 0; j < 32; ++j) {
        int o = h * 32 + j;
        ob[(size_t)o * HW] = acc[j] + xb[(size_t)o * HW];
    }
}

// ===========================================================================
extern "C" void kernel_launch(void* const* d_in, const int* in_sizes, int n_in,
                              void* d_out, int out_size)
{
    const float* x       = (const float*)d_in[0];
    const float* w_theta = (const float*)d_in[1];
    const float* b_theta = (const float*)d_in[2];
    const float* w_phi   = (const float*)d_in[3];
    const float* b_phi   = (const float*)d_in[4];
    const float* w_g     = (const float*)d_in[5];
    const float* b_g     = (const float*)d_in[6];
    const float* w_out   = (const float*)d_in[7];
    const float* b_out   = (const float*)d_in[8];
    float* out = (float*)d_out;

    conv_pool_kernel<<<dim3((Bsz * HW4 * 4) / 256, 2), 256>>>(x, w_phi, b_phi, w_g, b_g);

    cudaFuncSetAttribute(attn_fused_kernel,
                         cudaFuncAttributeMaxDynamicSharedMemorySize, SMEM_AT);
    attn_fused_kernel<<<dim3(128, Bsz, NSPL), 128, SMEM_AT>>>(x, w_theta, b_theta);

    combine_out_kernel<<<(Bsz * HW) / 128, 256>>>(x, w_out, b_out, out);
}